// round 13
// baseline (speedup 1.0000x reference)
#include <cuda_runtime.h>
#include <math.h>

#define NTOK 4096
#define DDIM 512
#define QKV  768
#define KSEL 819
#define SELPAD 832          // KSEL padded to multiple of 64
#define NCHUNK_C 13         // SELPAD / 64

// ---------------- scratch (device globals; no runtime allocation) -------------
__device__ float g_lqkv[NTOK * QKV];
__device__ float g_cqkv[NTOK * QKV];
__device__ float g_h[NTOK * 256];
__device__ float g_scores[NTOK];
__device__ int   g_mask[NTOK];
__device__ int   g_sel[SELPAD];
__device__ float g_m[8 * NTOK];
__device__ float g_invl[8 * NTOK];
__device__ float g_o[2 * NTOK * 256];   // [branch][tok][256]

// ---------------- fast exp on FMA/ALU pipes (MUFU-free) ------------------------
// rel err ~2e-6 for x<=0; valid for x in [-80, 0]. 2^f deg-5 poly + exponent splice.
__device__ __forceinline__ float fexp(float x) {
    float y = x * 1.44269504088896340736f;
    y = fmaxf(y, -126.0f);
    float z = y + 12582912.0f;            // round-to-nearest via magic number
    int   n = __float_as_int(z);          // low bits hold the rounded integer
    float f = y - (z - 12582912.0f);      // fractional part in [-0.5, 0.5]
    float p = 1.33335581e-3f;
    p = fmaf(p, f, 9.61812910e-3f);
    p = fmaf(p, f, 5.55041086e-2f);
    p = fmaf(p, f, 2.40226507e-1f);
    p = fmaf(p, f, 6.93147182e-1f);
    p = fmaf(p, f, 1.0f);
    return __int_as_float(__float_as_int(p) + (n << 23));
}

// ---------------- tf32 helpers ------------------------------------------------
__device__ __forceinline__ unsigned f2tf(float f) {
    unsigned r;
    asm("cvt.rna.tf32.f32 %0, %1;" : "=r"(r) : "f"(f));
    return r;
}
__device__ __forceinline__ void mma8(float& c0, float& c1, float& c2, float& c3,
                                     unsigned a0, unsigned a1, unsigned a2, unsigned a3,
                                     unsigned b0, unsigned b1)
{
    asm volatile(
        "mma.sync.aligned.m16n8k8.row.col.f32.tf32.tf32.f32 "
        "{%0,%1,%2,%3},{%4,%5,%6,%7},{%8,%9},{%0,%1,%2,%3};"
        : "+f"(c0), "+f"(c1), "+f"(c2), "+f"(c3)
        : "r"(a0), "r"(a1), "r"(a2), "r"(a3), "r"(b0), "r"(b1));
}

// ---------------- tf32 GEMM: C = A@W + bias ------------------------------------
__global__ __launch_bounds__(128) void proj_tf32(
    const float* __restrict__ A, const float* __restrict__ W,
    const float* __restrict__ bias, float* __restrict__ C, int Nc, int K)
{
    __shared__ unsigned Xs[128][36];
    __shared__ unsigned Ws[32][72];
    int t = threadIdx.x & 3, g = (threadIdx.x >> 2) & 7, w = threadIdx.x >> 5;
    int m0 = blockIdx.y * 128, n0 = blockIdx.x * 64;

    float acc[2][8][4];
#pragma unroll
    for (int mi = 0; mi < 2; mi++)
#pragma unroll
        for (int ni = 0; ni < 8; ni++)
#pragma unroll
            for (int c = 0; c < 4; c++) acc[mi][ni][c] = 0.f;

    for (int k0 = 0; k0 < K; k0 += 32) {
#pragma unroll
        for (int it = 0; it < 8; it++) {
            int idx = it * 128 + threadIdx.x;
            int row = idx >> 3, c4 = (idx & 7) * 4;
            float4 v = *(const float4*)&A[(size_t)(m0 + row) * K + k0 + c4];
            Xs[row][c4 + 0] = f2tf(v.x); Xs[row][c4 + 1] = f2tf(v.y);
            Xs[row][c4 + 2] = f2tf(v.z); Xs[row][c4 + 3] = f2tf(v.w);
        }
#pragma unroll
        for (int it = 0; it < 4; it++) {
            int idx = it * 128 + threadIdx.x;
            int kr = idx >> 4, n4 = (idx & 15) * 4;
            float4 v = *(const float4*)&W[(size_t)(k0 + kr) * Nc + n0 + n4];
            Ws[kr][n4 + 0] = f2tf(v.x); Ws[kr][n4 + 1] = f2tf(v.y);
            Ws[kr][n4 + 2] = f2tf(v.z); Ws[kr][n4 + 3] = f2tf(v.w);
        }
        __syncthreads();
#pragma unroll
        for (int ks = 0; ks < 4; ks++) {
            int kl = ks * 8;
            unsigned a[2][4];
#pragma unroll
            for (int mi = 0; mi < 2; mi++) {
                int r = w * 32 + mi * 16 + g;
                a[mi][0] = Xs[r][kl + t];      a[mi][1] = Xs[r + 8][kl + t];
                a[mi][2] = Xs[r][kl + t + 4];  a[mi][3] = Xs[r + 8][kl + t + 4];
            }
#pragma unroll
            for (int ni = 0; ni < 8; ni++) {
                unsigned b0 = Ws[kl + t][ni * 8 + g];
                unsigned b1 = Ws[kl + t + 4][ni * 8 + g];
#pragma unroll
                for (int mi = 0; mi < 2; mi++)
                    mma8(acc[mi][ni][0], acc[mi][ni][1], acc[mi][ni][2], acc[mi][ni][3],
                         a[mi][0], a[mi][1], a[mi][2], a[mi][3], b0, b1);
            }
        }
        __syncthreads();
    }
#pragma unroll
    for (int mi = 0; mi < 2; mi++)
#pragma unroll
        for (int ni = 0; ni < 8; ni++) {
            int m = m0 + w * 32 + mi * 16 + g;
            int n = n0 + ni * 8 + 2 * t;
            float bv0 = bias[n], bv1 = bias[n + 1];
            *(float2*)&C[(size_t)m * Nc + n] =
                make_float2(acc[mi][ni][0] + bv0, acc[mi][ni][1] + bv1);
            *(float2*)&C[(size_t)(m + 8) * Nc + n] =
                make_float2(acc[mi][ni][2] + bv0, acc[mi][ni][3] + bv1);
        }
}

// ------- merged output projection: out = [o_l|o_c] @ [W_l;W_c] + (b_l+b_c) ----
__global__ __launch_bounds__(128) void proj_out(
    const float* __restrict__ A, const float* __restrict__ Wl,
    const float* __restrict__ Wc, const float* __restrict__ bl,
    const float* __restrict__ bc, float* __restrict__ C)
{
    __shared__ unsigned Xs[128][36];
    __shared__ unsigned Ws[32][72];
    const int Nc = DDIM;
    int t = threadIdx.x & 3, g = (threadIdx.x >> 2) & 7, w = threadIdx.x >> 5;
    int m0 = blockIdx.y * 128, n0 = blockIdx.x * 64;

    float acc[2][8][4];
#pragma unroll
    for (int mi = 0; mi < 2; mi++)
#pragma unroll
        for (int ni = 0; ni < 8; ni++)
#pragma unroll
            for (int c = 0; c < 4; c++) acc[mi][ni][c] = 0.f;

    for (int k0 = 0; k0 < 512; k0 += 32) {
        size_t abase = (k0 >= 256) ? (size_t)NTOK * 256 : 0;
        int kcol = k0 & 255;
        const float* Wp = (k0 >= 256) ? Wc : Wl;
#pragma unroll
        for (int it = 0; it < 8; it++) {
            int idx = it * 128 + threadIdx.x;
            int row = idx >> 3, c4 = (idx & 7) * 4;
            float4 v = *(const float4*)&A[abase + (size_t)(m0 + row) * 256 + kcol + c4];
            Xs[row][c4 + 0] = f2tf(v.x); Xs[row][c4 + 1] = f2tf(v.y);
            Xs[row][c4 + 2] = f2tf(v.z); Xs[row][c4 + 3] = f2tf(v.w);
        }
#pragma unroll
        for (int it = 0; it < 4; it++) {
            int idx = it * 128 + threadIdx.x;
            int kr = idx >> 4, n4 = (idx & 15) * 4;
            float4 v = *(const float4*)&Wp[(size_t)(kcol + kr) * Nc + n0 + n4];
            Ws[kr][n4 + 0] = f2tf(v.x); Ws[kr][n4 + 1] = f2tf(v.y);
            Ws[kr][n4 + 2] = f2tf(v.z); Ws[kr][n4 + 3] = f2tf(v.w);
        }
        __syncthreads();
#pragma unroll
        for (int ks = 0; ks < 4; ks++) {
            int kl = ks * 8;
            unsigned a[2][4];
#pragma unroll
            for (int mi = 0; mi < 2; mi++) {
                int r = w * 32 + mi * 16 + g;
                a[mi][0] = Xs[r][kl + t];      a[mi][1] = Xs[r + 8][kl + t];
                a[mi][2] = Xs[r][kl + t + 4];  a[mi][3] = Xs[r + 8][kl + t + 4];
            }
#pragma unroll
            for (int ni = 0; ni < 8; ni++) {
                unsigned b0 = Ws[kl + t][ni * 8 + g];
                unsigned b1 = Ws[kl + t + 4][ni * 8 + g];
#pragma unroll
                for (int mi = 0; mi < 2; mi++)
                    mma8(acc[mi][ni][0], acc[mi][ni][1], acc[mi][ni][2], acc[mi][ni][3],
                         a[mi][0], a[mi][1], a[mi][2], a[mi][3], b0, b1);
            }
        }
        __syncthreads();
    }
#pragma unroll
    for (int mi = 0; mi < 2; mi++)
#pragma unroll
        for (int ni = 0; ni < 8; ni++) {
            int m = m0 + w * 32 + mi * 16 + g;
            int n = n0 + ni * 8 + 2 * t;
            float bv0 = bl[n] + bc[n], bv1 = bl[n + 1] + bc[n + 1];
            *(float2*)&C[(size_t)m * Nc + n] =
                make_float2(acc[mi][ni][0] + bv0, acc[mi][ni][1] + bv1);
            *(float2*)&C[(size_t)(m + 8) * Nc + n] =
                make_float2(acc[mi][ni][2] + bv0, acc[mi][ni][3] + bv1);
        }
}

// ---------------- 3xTF32 error-compensated GEMM + exact GELU (saliency s1) ----
__global__ __launch_bounds__(128) void s1_tf32x3(
    const float* __restrict__ A, const float* __restrict__ W,
    const float* __restrict__ bias, float* __restrict__ C, int Nc, int K)
{
    __shared__ unsigned Xhi[64][36], Xlo[64][36];
    __shared__ unsigned Whi[32][72], Wlo[32][72];
    int t = threadIdx.x & 3, g = (threadIdx.x >> 2) & 7, w = threadIdx.x >> 5;
    int m0 = blockIdx.y * 64, n0 = blockIdx.x * 64;

    float acc[8][4];
#pragma unroll
    for (int ni = 0; ni < 8; ni++)
#pragma unroll
        for (int c = 0; c < 4; c++) acc[ni][c] = 0.f;

    for (int k0 = 0; k0 < K; k0 += 32) {
#pragma unroll
        for (int it = 0; it < 4; it++) {
            int idx = it * 128 + threadIdx.x;
            int row = idx >> 3, c4 = (idx & 7) * 4;
            float4 v = *(const float4*)&A[(size_t)(m0 + row) * K + k0 + c4];
            float vv[4] = {v.x, v.y, v.z, v.w};
#pragma unroll
            for (int j = 0; j < 4; j++) {
                unsigned hi = f2tf(vv[j]);
                Xhi[row][c4 + j] = hi;
                Xlo[row][c4 + j] = f2tf(vv[j] - __uint_as_float(hi));
            }
        }
#pragma unroll
        for (int it = 0; it < 4; it++) {
            int idx = it * 128 + threadIdx.x;
            int kr = idx >> 4, n4 = (idx & 15) * 4;
            float4 v = *(const float4*)&W[(size_t)(k0 + kr) * Nc + n0 + n4];
            float vv[4] = {v.x, v.y, v.z, v.w};
#pragma unroll
            for (int j = 0; j < 4; j++) {
                unsigned hi = f2tf(vv[j]);
                Whi[kr][n4 + j] = hi;
                Wlo[kr][n4 + j] = f2tf(vv[j] - __uint_as_float(hi));
            }
        }
        __syncthreads();
#pragma unroll
        for (int ks = 0; ks < 4; ks++) {
            int kl = ks * 8;
            int r = w * 16 + g;
            unsigned ah[4], al[4];
            ah[0] = Xhi[r][kl + t];      ah[1] = Xhi[r + 8][kl + t];
            ah[2] = Xhi[r][kl + t + 4];  ah[3] = Xhi[r + 8][kl + t + 4];
            al[0] = Xlo[r][kl + t];      al[1] = Xlo[r + 8][kl + t];
            al[2] = Xlo[r][kl + t + 4];  al[3] = Xlo[r + 8][kl + t + 4];
#pragma unroll
            for (int ni = 0; ni < 8; ni++) {
                unsigned bh0 = Whi[kl + t][ni * 8 + g];
                unsigned bh1 = Whi[kl + t + 4][ni * 8 + g];
                unsigned bl0 = Wlo[kl + t][ni * 8 + g];
                unsigned bl1 = Wlo[kl + t + 4][ni * 8 + g];
                mma8(acc[ni][0], acc[ni][1], acc[ni][2], acc[ni][3],
                     al[0], al[1], al[2], al[3], bh0, bh1);
                mma8(acc[ni][0], acc[ni][1], acc[ni][2], acc[ni][3],
                     ah[0], ah[1], ah[2], ah[3], bl0, bl1);
                mma8(acc[ni][0], acc[ni][1], acc[ni][2], acc[ni][3],
                     ah[0], ah[1], ah[2], ah[3], bh0, bh1);
            }
        }
        __syncthreads();
    }
#pragma unroll
    for (int ni = 0; ni < 8; ni++) {
        int m = m0 + w * 16 + g;
        int n = n0 + ni * 8 + 2 * t;
        float bv0 = bias[n], bv1 = bias[n + 1];
        float vv[4] = {acc[ni][0] + bv0, acc[ni][1] + bv1,
                       acc[ni][2] + bv0, acc[ni][3] + bv1};
#pragma unroll
        for (int j = 0; j < 4; j++)
            vv[j] = 0.5f * vv[j] * (1.0f + erff(vv[j] * 0.70710678118654752f));
        *(float2*)&C[(size_t)m * Nc + n] = make_float2(vv[0], vv[1]);
        *(float2*)&C[(size_t)(m + 8) * Nc + n] = make_float2(vv[2], vv[3]);
    }
}

// ---------------- flash attention (fast exp; shfl transpose) -------------------
#define FLASH_SMEM ((128*68 + 64*68 + 64*72 + 64) * 4)
__global__ __launch_bounds__(256, 2) void flash_kernel()
{
    extern __shared__ unsigned sm[];
    unsigned* Qs = sm;                 // [128][68]
    unsigned* Ks = Qs + 128 * 68;      // [64][68]
    unsigned* Vs = Ks + 64 * 68;       // [64][72]
    int* maskCh  = (int*)(Vs + 64 * 72);   // [64]

    int hb = blockIdx.y;
    const float* buf = (hb < 4) ? g_lqkv : g_cqkv;
    int h = hb & 3;
    bool content = hb >= 4;
    int q0 = blockIdx.x * 128;
    int tid = threadIdx.x, lane = tid & 31, w = tid >> 5;
    int t = lane & 3, g = lane >> 2;
    int rb = w * 16 + g;
    int srcA = (g << 2) | (t >> 1);
    int srcB = srcA + 2;
    bool oddt = (t & 1);

#pragma unroll
    for (int it = 0; it < 8; it++) {
        int idx = it * 256 + tid;
        int r = idx >> 4, c = (idx & 15) * 4;
        float4 v = *(const float4*)&buf[(size_t)(q0 + r) * QKV + h * 64 + c];
        Qs[r * 68 + c + 0] = f2tf(v.x); Qs[r * 68 + c + 1] = f2tf(v.y);
        Qs[r * 68 + c + 2] = f2tf(v.z); Qs[r * 68 + c + 3] = f2tf(v.w);
    }

    float m0 = -1e30f, m1 = -1e30f, l0 = 0.f, l1 = 0.f;
    float oacc[8][4];
#pragma unroll
    for (int ni = 0; ni < 8; ni++)
#pragma unroll
        for (int c = 0; c < 4; c++) oacc[ni][c] = 0.f;

    int nch = content ? NCHUNK_C : (NTOK / 64);
    for (int ch = 0; ch < nch; ch++) {
        int kc = ch * 64;
        __syncthreads();
#pragma unroll
        for (int it = 0; it < 4; it++) {
            int idx = it * 256 + tid;
            int r = idx >> 4, c = (idx & 15) * 4;
            int srow = content ? g_sel[kc + r] : (kc + r);
            int rr = srow < 0 ? 0 : srow;
            float4 kv = *(const float4*)&buf[(size_t)rr * QKV + 256 + h * 64 + c];
            Ks[r * 68 + c + 0] = f2tf(kv.x); Ks[r * 68 + c + 1] = f2tf(kv.y);
            Ks[r * 68 + c + 2] = f2tf(kv.z); Ks[r * 68 + c + 3] = f2tf(kv.w);
            float4 vv = *(const float4*)&buf[(size_t)rr * QKV + 512 + h * 64 + c];
            Vs[r * 72 + c + 0] = f2tf(vv.x); Vs[r * 72 + c + 1] = f2tf(vv.y);
            Vs[r * 72 + c + 2] = f2tf(vv.z); Vs[r * 72 + c + 3] = f2tf(vv.w);
        }
        if (tid < 64) maskCh[tid] = content ? (g_sel[kc + tid] >= 0) : 1;
        __syncthreads();

        float sacc[8][4];
#pragma unroll
        for (int ni = 0; ni < 8; ni++)
#pragma unroll
            for (int c = 0; c < 4; c++) sacc[ni][c] = 0.f;
#pragma unroll
        for (int ks = 0; ks < 8; ks++) {
            int kl = ks * 8;
            unsigned a0 = Qs[rb * 68 + kl + t];
            unsigned a1 = Qs[(rb + 8) * 68 + kl + t];
            unsigned a2 = Qs[rb * 68 + kl + t + 4];
            unsigned a3 = Qs[(rb + 8) * 68 + kl + t + 4];
#pragma unroll
            for (int ni = 0; ni < 8; ni++) {
                unsigned b0 = Ks[(ni * 8 + g) * 68 + kl + t];
                unsigned b1 = Ks[(ni * 8 + g) * 68 + kl + t + 4];
                mma8(sacc[ni][0], sacc[ni][1], sacc[ni][2], sacc[ni][3],
                     a0, a1, a2, a3, b0, b1);
            }
        }
        float cm0 = -1e30f, cm1 = -1e30f;
#pragma unroll
        for (int ni = 0; ni < 8; ni++) {
            int c0 = ni * 8 + 2 * t;
            bool on0 = maskCh[c0];
            bool on1 = maskCh[c0 + 1];
            sacc[ni][0] *= 0.125f; sacc[ni][1] *= 0.125f;
            sacc[ni][2] *= 0.125f; sacc[ni][3] *= 0.125f;
            cm0 = fmaxf(cm0, fmaxf(on0 ? sacc[ni][0] : -1e30f, on1 ? sacc[ni][1] : -1e30f));
            cm1 = fmaxf(cm1, fmaxf(on0 ? sacc[ni][2] : -1e30f, on1 ? sacc[ni][3] : -1e30f));
        }
        cm0 = fmaxf(cm0, __shfl_xor_sync(0xffffffffu, cm0, 1));
        cm0 = fmaxf(cm0, __shfl_xor_sync(0xffffffffu, cm0, 2));
        cm1 = fmaxf(cm1, __shfl_xor_sync(0xffffffffu, cm1, 1));
        cm1 = fmaxf(cm1, __shfl_xor_sync(0xffffffffu, cm1, 2));

        float mn0 = fmaxf(m0, cm0), mn1 = fmaxf(m1, cm1);
        float r0 = fexp(m0 - mn0), r1 = fexp(m1 - mn1);
        m0 = mn0; m1 = mn1;

        float es0 = 0.f, es1 = 0.f;
#pragma unroll
        for (int ni = 0; ni < 8; ni++) {
            int c0 = ni * 8 + 2 * t;
            bool on0 = maskCh[c0];
            bool on1 = maskCh[c0 + 1];
            float e00 = on0 ? fexp(sacc[ni][0] - mn0) : 0.f;
            float e01 = on1 ? fexp(sacc[ni][1] - mn0) : 0.f;
            float e10 = on0 ? fexp(sacc[ni][2] - mn1) : 0.f;
            float e11 = on1 ? fexp(sacc[ni][3] - mn1) : 0.f;
            es0 += e00 + e01; es1 += e10 + e11;
            sacc[ni][0] = e00; sacc[ni][1] = e01;
            sacc[ni][2] = e10; sacc[ni][3] = e11;
        }
        es0 += __shfl_xor_sync(0xffffffffu, es0, 1);
        es0 += __shfl_xor_sync(0xffffffffu, es0, 2);
        es1 += __shfl_xor_sync(0xffffffffu, es1, 1);
        es1 += __shfl_xor_sync(0xffffffffu, es1, 2);
        l0 = l0 * r0 + es0;
        l1 = l1 * r1 + es1;
#pragma unroll
        for (int ni = 0; ni < 8; ni++) {
            oacc[ni][0] *= r0; oacc[ni][1] *= r0;
            oacc[ni][2] *= r1; oacc[ni][3] *= r1;
        }

#pragma unroll
        for (int ks = 0; ks < 8; ks++) {
            float v00 = __shfl_sync(0xffffffffu, sacc[ks][0], srcA);
            float v01 = __shfl_sync(0xffffffffu, sacc[ks][1], srcA);
            float v10 = __shfl_sync(0xffffffffu, sacc[ks][2], srcA);
            float v11 = __shfl_sync(0xffffffffu, sacc[ks][3], srcA);
            float w00 = __shfl_sync(0xffffffffu, sacc[ks][0], srcB);
            float w01 = __shfl_sync(0xffffffffu, sacc[ks][1], srcB);
            float w10 = __shfl_sync(0xffffffffu, sacc[ks][2], srcB);
            float w11 = __shfl_sync(0xffffffffu, sacc[ks][3], srcB);
            unsigned a0 = f2tf(oddt ? v01 : v00);
            unsigned a1 = f2tf(oddt ? v11 : v10);
            unsigned a2 = f2tf(oddt ? w01 : w00);
            unsigned a3 = f2tf(oddt ? w11 : w10);
            int kl = ks * 8;
#pragma unroll
            for (int ni = 0; ni < 8; ni++) {
                unsigned b0 = Vs[(kl + t) * 72 + ni * 8 + g];
                unsigned b1 = Vs[(kl + t + 4) * 72 + ni * 8 + g];
                mma8(oacc[ni][0], oacc[ni][1], oacc[ni][2], oacc[ni][3],
                     a0, a1, a2, a3, b0, b1);
            }
        }
    }

    float iv0 = 1.0f / l0, iv1 = 1.0f / l1;
    int bB = hb >> 2;
    size_t ob = (size_t)bB * NTOK * 256;
    int r0i = q0 + rb, r1i = r0i + 8;
#pragma unroll
    for (int ni = 0; ni < 8; ni++) {
        int d = h * 64 + ni * 8 + 2 * t;
        *(float2*)&g_o[ob + (size_t)r0i * 256 + d] =
            make_float2(oacc[ni][0] * iv0, oacc[ni][1] * iv0);
        *(float2*)&g_o[ob + (size_t)r1i * 256 + d] =
            make_float2(oacc[ni][2] * iv1, oacc[ni][3] * iv1);
    }
    if (t == 0) {
        g_invl[hb * NTOK + r0i] = iv0; g_invl[hb * NTOK + r1i] = iv1;
        g_m[hb * NTOK + r0i] = m0;     g_m[hb * NTOK + r1i] = m1;
    }
}

// ---------------- attn local half: dense recompute + head-mean (512 thr) ------
#define ATTNL_SMEM ((128*68 + 128*68) * 4)
__global__ __launch_bounds__(512) void attn_local(float* __restrict__ attn)
{
    extern __shared__ unsigned sm[];
    unsigned* Qs = sm;                 // [128][68]
    unsigned* Ks = Qs + 128 * 68;      // [128][68]

    const float* buf = g_lqkv;
    int q0 = blockIdx.y * 128, k0 = blockIdx.x * 128;
    int tid = threadIdx.x, lane = tid & 31, w = tid >> 5;
    int t = lane & 3, g = lane >> 2;
    int wq = w & 7, wk = w >> 3;
    int rb = wq * 16 + g;
    int kb = wk * 64;
    int r0i = q0 + rb, r1i = r0i + 8;

    float mh[4][2], iv[4][2];
#pragma unroll
    for (int h = 0; h < 4; h++) {
        mh[h][0] = g_m[h * NTOK + r0i];
        mh[h][1] = g_m[h * NTOK + r1i];
        iv[h][0] = g_invl[h * NTOK + r0i];
        iv[h][1] = g_invl[h * NTOK + r1i];
    }

    float facc[8][4];
#pragma unroll
    for (int ni = 0; ni < 8; ni++)
#pragma unroll
        for (int c = 0; c < 4; c++) facc[ni][c] = 0.f;

    for (int h = 0; h < 4; h++) {
        __syncthreads();
#pragma unroll
        for (int it = 0; it < 4; it++) {
            int idx = it * 512 + tid;
            int r = idx >> 4, c = (idx & 15) * 4;
            float4 v = *(const float4*)&buf[(size_t)(q0 + r) * QKV + h * 64 + c];
            Qs[r * 68 + c + 0] = f2tf(v.x); Qs[r * 68 + c + 1] = f2tf(v.y);
            Qs[r * 68 + c + 2] = f2tf(v.z); Qs[r * 68 + c + 3] = f2tf(v.w);
            float4 u = *(const float4*)&buf[(size_t)(k0 + r) * QKV + 256 + h * 64 + c];
            Ks[r * 68 + c + 0] = f2tf(u.x); Ks[r * 68 + c + 1] = f2tf(u.y);
            Ks[r * 68 + c + 2] = f2tf(u.z); Ks[r * 68 + c + 3] = f2tf(u.w);
        }
        __syncthreads();

        float sacc[8][4];
#pragma unroll
        for (int ni = 0; ni < 8; ni++)
#pragma unroll
            for (int c = 0; c < 4; c++) sacc[ni][c] = 0.f;
#pragma unroll
        for (int ks = 0; ks < 8; ks++) {
            int kl = ks * 8;
            unsigned a0 = Qs[rb * 68 + kl + t];
            unsigned a1 = Qs[(rb + 8) * 68 + kl + t];
            unsigned a2 = Qs[rb * 68 + kl + t + 4];
            unsigned a3 = Qs[(rb + 8) * 68 + kl + t + 4];
#pragma unroll
            for (int ni = 0; ni < 8; ni++) {
                unsigned b0 = Ks[(kb + ni * 8 + g) * 68 + kl + t];
                unsigned b1 = Ks[(kb + ni * 8 + g) * 68 + kl + t + 4];
                mma8(sacc[ni][0], sacc[ni][1], sacc[ni][2], sacc[ni][3],
                     a0, a1, a2, a3, b0, b1);
            }
        }
#pragma unroll
        for (int ni = 0; ni < 8; ni++) {
            facc[ni][0] += fexp(sacc[ni][0] * 0.125f - mh[h][0]) * iv[h][0];
            facc[ni][1] += fexp(sacc[ni][1] * 0.125f - mh[h][0]) * iv[h][0];
            facc[ni][2] += fexp(sacc[ni][2] * 0.125f - mh[h][1]) * iv[h][1];
            facc[ni][3] += fexp(sacc[ni][3] * 0.125f - mh[h][1]) * iv[h][1];
        }
    }
#pragma unroll
    for (int ni = 0; ni < 8; ni++) {
        int kk = k0 + kb + ni * 8 + 2 * t;
        *(float2*)&attn[(size_t)r0i * NTOK + kk] =
            make_float2(facc[ni][0] * 0.25f, facc[ni][1] * 0.25f);
        *(float2*)&attn[(size_t)r1i * NTOK + kk] =
            make_float2(facc[ni][2] * 0.25f, facc[ni][3] * 0.25f);
    }
}

// ---------------- attn content half: only selected columns --------------------
#define ATTNC_SMEM ((128*68 + 64*68 + 64) * 4)
__global__ __launch_bounds__(256) void attn_content(float* __restrict__ attn)
{
    extern __shared__ unsigned sm[];
    unsigned* Qs = sm;                 // [128][68]
    unsigned* Ks = Qs + 128 * 68;      // [64][68]
    int* selS    = (int*)(Ks + 64 * 68);   // [64]

    const float* buf = g_cqkv;
    int q0 = blockIdx.y * 128;
    int k0s = blockIdx.x * 64;
    int tid = threadIdx.x, lane = tid & 31, w = tid >> 5;
    int t = lane & 3, g = lane >> 2;
    int rb = w * 16 + g;
    int r0i = q0 + rb, r1i = r0i + 8;

    if (tid < 64) selS[tid] = g_sel[k0s + tid];

    float mh[4][2], iv[4][2];
#pragma unroll
    for (int h = 0; h < 4; h++) {
        mh[h][0] = g_m[(4 + h) * NTOK + r0i];
        mh[h][1] = g_m[(4 + h) * NTOK + r1i];
        iv[h][0] = g_invl[(4 + h) * NTOK + r0i];
        iv[h][1] = g_invl[(4 + h) * NTOK + r1i];
    }

    float facc[8][4];
#pragma unroll
    for (int ni = 0; ni < 8; ni++)
#pragma unroll
        for (int c = 0; c < 4; c++) facc[ni][c] = 0.f;

    for (int h = 0; h < 4; h++) {
        __syncthreads();
#pragma unroll
        for (int it = 0; it < 8; it++) {
            int idx = it * 256 + tid;
            int r = idx >> 4, c = (idx & 15) * 4;
            float4 v = *(const float4*)&buf[(size_t)(q0 + r) * QKV + h * 64 + c];
            Qs[r * 68 + c + 0] = f2tf(v.x); Qs[r * 68 + c + 1] = f2tf(v.y);
            Qs[r * 68 + c + 2] = f2tf(v.z); Qs[r * 68 + c + 3] = f2tf(v.w);
        }
#pragma unroll
        for (int it = 0; it < 4; it++) {
            int idx = it * 256 + tid;
            int r = idx >> 4, c = (idx & 15) * 4;
            int srow = selS[r];
            int rr = srow < 0 ? 0 : srow;
            float4 u = *(const float4*)&buf[(size_t)rr * QKV + 256 + h * 64 + c];
            Ks[r * 68 + c + 0] = f2tf(u.x); Ks[r * 68 + c + 1] = f2tf(u.y);
            Ks[r * 68 + c + 2] = f2tf(u.z); Ks[r * 68 + c + 3] = f2tf(u.w);
        }
        __syncthreads();

        float sacc[8][4];
#pragma unroll
        for (int ni = 0; ni < 8; ni++)
#pragma unroll
            for (int c = 0; c < 4; c++) sacc[ni][c] = 0.f;
#pragma unroll
        for (int ks = 0; ks < 8; ks++) {
            int kl = ks * 8;
            unsigned a0 = Qs[rb * 68 + kl + t];
            unsigned a1 = Qs[(rb + 8) * 68 + kl + t];
            unsigned a2 = Qs[rb * 68 + kl + t + 4];
            unsigned a3 = Qs[(rb + 8) * 68 + kl + t + 4];
#pragma unroll
            for (int ni = 0; ni < 8; ni++) {
                unsigned b0 = Ks[(ni * 8 + g) * 68 + kl + t];
                unsigned b1 = Ks[(ni * 8 + g) * 68 + kl + t + 4];
                mma8(sacc[ni][0], sacc[ni][1], sacc[ni][2], sacc[ni][3],
                     a0, a1, a2, a3, b0, b1);
            }
        }
#pragma unroll
        for (int ni = 0; ni < 8; ni++) {
            facc[ni][0] += fexp(sacc[ni][0] * 0.125f - mh[h][0]) * iv[h][0];
            facc[ni][1] += fexp(sacc[ni][1] * 0.125f - mh[h][0]) * iv[h][0];
            facc[ni][2] += fexp(sacc[ni][2] * 0.125f - mh[h][1]) * iv[h][1];
            facc[ni][3] += fexp(sacc[ni][3] * 0.125f - mh[h][1]) * iv[h][1];
        }
    }
    float* arow0 = attn + ((size_t)(NTOK + r0i)) * NTOK;
    float* arow1 = attn + ((size_t)(NTOK + r1i)) * NTOK;
#pragma unroll
    for (int ni = 0; ni < 8; ni++) {
        int c0 = ni * 8 + 2 * t;
        int s0 = selS[c0], s1 = selS[c0 + 1];
        if (s0 >= 0) {
            arow0[s0] = facc[ni][0] * 0.25f;
            arow1[s0] = facc[ni][2] * 0.25f;
        }
        if (s1 >= 0) {
            arow0[s1] = facc[ni][1] * 0.25f;
            arow1[s1] = facc[ni][3] * 0.25f;
        }
    }
}

// ---------------- zero-fill content attn half ---------------------------------
__global__ __launch_bounds__(256) void fill_zero(float* __restrict__ p)
{
    size_t base = ((size_t)blockIdx.x * 256 + threadIdx.x) * 16;
    float4 z = make_float4(0.f, 0.f, 0.f, 0.f);
#pragma unroll
    for (int i = 0; i < 4; i++)
        *(float4*)&p[base + i * 4] = z;
}

// ---------------- saliency scores + exact top-k mask + compaction -------------
__global__ __launch_bounds__(256) void scores_kernel(
    const float* __restrict__ Ws2, const float* __restrict__ bs2)
{
    int t = blockIdx.x * 8 + (threadIdx.x >> 5);
    int lane = threadIdx.x & 31;
    const float* hp = g_h + (size_t)t * 256;
    float s = 0.f;
    for (int i = lane; i < 256; i += 32) s += hp[i] * Ws2[i];
#pragma unroll
    for (int off = 16; off; off >>= 1) s += __shfl_xor_sync(0xffffffffu, s, off);
    if (lane == 0) g_scores[t] = s + bs2[0];
}

__global__ __launch_bounds__(256) void mask_kernel()
{
    __shared__ float sc[NTOK];
    for (int i = threadIdx.x; i < NTOK; i += 256) sc[i] = g_scores[i];
    __syncthreads();
    int i = blockIdx.x * 256 + threadIdx.x;
    float si = sc[i];
    int cnt = 0;
    for (int j = 0; j < NTOK; j++) {
        float sj = sc[j];
        cnt += (sj > si) || (sj == si && j < i);
    }
    g_mask[i] = (cnt < KSEL) ? 1 : 0;
}

__global__ __launch_bounds__(1024) void compact_kernel()
{
    __shared__ int pre[1024];
    int tid = threadIdx.x;
    int base = tid * 4;
    int m0 = g_mask[base], m1 = g_mask[base + 1];
    int m2 = g_mask[base + 2], m3 = g_mask[base + 3];
    int s = m0 + m1 + m2 + m3;
    pre[tid] = s;
    __syncthreads();
    for (int off = 1; off < 1024; off <<= 1) {
        int v = (tid >= off) ? pre[tid - off] : 0;
        __syncthreads();
        pre[tid] += v;
        __syncthreads();
    }
    int p = pre[tid] - s;
    if (m0) g_sel[p++] = base;
    if (m1) g_sel[p++] = base + 1;
    if (m2) g_sel[p++] = base + 2;
    if (m3) g_sel[p++] = base + 3;
    if (tid < SELPAD - KSEL) g_sel[KSEL + tid] = -1;
}

// -----------------------------------------------------------------------------
extern "C" void kernel_launch(void* const* d_in, const int* in_sizes, int n_in,
                              void* d_out, int out_size)
{
    const float* x       = (const float*)d_in[0];
    const float* W_lqkv  = (const float*)d_in[1];
    const float* b_lqkv  = (const float*)d_in[2];
    const float* W_cqkv  = (const float*)d_in[3];
    const float* b_cqkv  = (const float*)d_in[4];
    const float* W_lproj = (const float*)d_in[5];
    const float* b_lproj = (const float*)d_in[6];
    const float* W_cproj = (const float*)d_in[7];
    const float* b_cproj = (const float*)d_in[8];
    const float* W_s1    = (const float*)d_in[9];
    const float* b_s1    = (const float*)d_in[10];
    const float* W_s2    = (const float*)d_in[11];
    const float* b_s2    = (const float*)d_in[12];

    float* out  = (float*)d_out;
    float* attn = out + (size_t)NTOK * DDIM;

    float *p_lqkv, *p_cqkv, *p_h, *p_o;
    cudaGetSymbolAddress((void**)&p_lqkv, g_lqkv);
    cudaGetSymbolAddress((void**)&p_cqkv, g_cqkv);
    cudaGetSymbolAddress((void**)&p_h,    g_h);
    cudaGetSymbolAddress((void**)&p_o,    g_o);

    static int attr_done = 0;
    if (!attr_done) {
        cudaFuncSetAttribute(flash_kernel,
            cudaFuncAttributeMaxDynamicSharedMemorySize, FLASH_SMEM);
        cudaFuncSetAttribute(attn_local,
            cudaFuncAttributeMaxDynamicSharedMemorySize, ATTNL_SMEM);
        cudaFuncSetAttribute(attn_content,
            cudaFuncAttributeMaxDynamicSharedMemorySize, ATTNC_SMEM);
        attr_done = 1;
    }

    // QKV projections (tf32 tensor cores)
    proj_tf32<<<dim3(12, 32), 128>>>(x, W_lqkv, b_lqkv, p_lqkv, QKV, DDIM);
    proj_tf32<<<dim3(12, 32), 128>>>(x, W_cqkv, b_cqkv, p_cqkv, QKV, DDIM);

    // saliency path (3xTF32 — fp32-equivalent accuracy, protects top-k boundary)
    s1_tf32x3<<<dim3(4, 64), 128>>>(x, W_s1, b_s1, p_h, 256, DDIM);
    scores_kernel<<<512, 256>>>(W_s2, b_s2);
    mask_kernel<<<16, 256>>>();
    compact_kernel<<<1, 1024>>>();

    // zero-fill content attn half (overwritten at selected columns below)
    fill_zero<<<4096, 256>>>(attn + (size_t)NTOK * NTOK);

    // attention core (flash; content heads use compacted key list)
    flash_kernel<<<dim3(32, 8), 256, FLASH_SMEM>>>();

    // attn output halves
    attn_local<<<dim3(32, 32), 512, ATTNL_SMEM>>>(attn);
    attn_content<<<dim3(NCHUNK_C, 32), 256, ATTNC_SMEM>>>(attn);

    // merged output projection: out = [o_l|o_c] @ [W_l;W_c] + (b_l+b_c)
    proj_out<<<dim3(8, 32), 128>>>(p_o, W_lproj, W_cproj, b_lproj, b_cproj, out);
}

// round 14
// speedup vs baseline: 1.0959x; 1.0959x over previous
#include <cuda_runtime.h>
#include <math.h>

#define NTOK 4096
#define DDIM 512
#define QKV  768
#define KSEL 819
#define SELPAD 832          // KSEL padded to multiple of 64
#define NCHUNK_C 13         // SELPAD / 64

// ---------------- scratch (device globals; no runtime allocation) -------------
__device__ float g_lqkv[NTOK * QKV];
__device__ float g_cqkv[NTOK * QKV];
__device__ float g_h[NTOK * 256];
__device__ float g_scores[NTOK];
__device__ int   g_mask[NTOK];
__device__ int   g_sel[SELPAD];
__device__ float g_m[8 * NTOK];
__device__ float g_invl[8 * NTOK];
__device__ float g_o[2 * NTOK * 256];

// ---------------- tf32 helpers ------------------------------------------------
__device__ __forceinline__ unsigned f2tf(float f) {
    unsigned r;
    asm("cvt.rna.tf32.f32 %0, %1;" : "=r"(r) : "f"(f));
    return r;
}
__device__ __forceinline__ void mma8(float& c0, float& c1, float& c2, float& c3,
                                     unsigned a0, unsigned a1, unsigned a2, unsigned a3,
                                     unsigned b0, unsigned b1)
{
    asm volatile(
        "mma.sync.aligned.m16n8k8.row.col.f32.tf32.tf32.f32 "
        "{%0,%1,%2,%3},{%4,%5,%6,%7},{%8,%9},{%0,%1,%2,%3};"
        : "+f"(c0), "+f"(c1), "+f"(c2), "+f"(c3)
        : "r"(a0), "r"(a1), "r"(a2), "r"(a3), "r"(b0), "r"(b1));
}

// ---------------- tf32 GEMM: C = A@W + bias (opt accumulate into C) -----------
__global__ __launch_bounds__(128) void proj_tf32(
    const float* __restrict__ A, const float* __restrict__ W,
    const float* __restrict__ bias, float* __restrict__ C, int Nc, int K,
    int accum)
{
    __shared__ unsigned Xs[128][36];
    __shared__ unsigned Ws[32][72];
    int t = threadIdx.x & 3, g = (threadIdx.x >> 2) & 7, w = threadIdx.x >> 5;
    int m0 = blockIdx.y * 128, n0 = blockIdx.x * 64;

    float acc[2][8][4];
#pragma unroll
    for (int mi = 0; mi < 2; mi++)
#pragma unroll
        for (int ni = 0; ni < 8; ni++)
#pragma unroll
            for (int c = 0; c < 4; c++) acc[mi][ni][c] = 0.f;

    for (int k0 = 0; k0 < K; k0 += 32) {
#pragma unroll
        for (int it = 0; it < 8; it++) {
            int idx = it * 128 + threadIdx.x;
            int row = idx >> 3, c4 = (idx & 7) * 4;
            float4 v = *(const float4*)&A[(size_t)(m0 + row) * K + k0 + c4];
            Xs[row][c4 + 0] = f2tf(v.x); Xs[row][c4 + 1] = f2tf(v.y);
            Xs[row][c4 + 2] = f2tf(v.z); Xs[row][c4 + 3] = f2tf(v.w);
        }
#pragma unroll
        for (int it = 0; it < 4; it++) {
            int idx = it * 128 + threadIdx.x;
            int kr = idx >> 4, n4 = (idx & 15) * 4;
            float4 v = *(const float4*)&W[(size_t)(k0 + kr) * Nc + n0 + n4];
            Ws[kr][n4 + 0] = f2tf(v.x); Ws[kr][n4 + 1] = f2tf(v.y);
            Ws[kr][n4 + 2] = f2tf(v.z); Ws[kr][n4 + 3] = f2tf(v.w);
        }
        __syncthreads();
#pragma unroll
        for (int ks = 0; ks < 4; ks++) {
            int kl = ks * 8;
            unsigned a[2][4];
#pragma unroll
            for (int mi = 0; mi < 2; mi++) {
                int r = w * 32 + mi * 16 + g;
                a[mi][0] = Xs[r][kl + t];      a[mi][1] = Xs[r + 8][kl + t];
                a[mi][2] = Xs[r][kl + t + 4];  a[mi][3] = Xs[r + 8][kl + t + 4];
            }
#pragma unroll
            for (int ni = 0; ni < 8; ni++) {
                unsigned b0 = Ws[kl + t][ni * 8 + g];
                unsigned b1 = Ws[kl + t + 4][ni * 8 + g];
#pragma unroll
                for (int mi = 0; mi < 2; mi++)
                    mma8(acc[mi][ni][0], acc[mi][ni][1], acc[mi][ni][2], acc[mi][ni][3],
                         a[mi][0], a[mi][1], a[mi][2], a[mi][3], b0, b1);
            }
        }
        __syncthreads();
    }
#pragma unroll
    for (int mi = 0; mi < 2; mi++)
#pragma unroll
        for (int ni = 0; ni < 8; ni++) {
            int m = m0 + w * 32 + mi * 16 + g;
            int n = n0 + ni * 8 + 2 * t;
            float bv0 = bias[n], bv1 = bias[n + 1];
            float v00 = acc[mi][ni][0] + bv0, v01 = acc[mi][ni][1] + bv1;
            float v10 = acc[mi][ni][2] + bv0, v11 = acc[mi][ni][3] + bv1;
            float* p0 = &C[(size_t)m * Nc + n];
            float* p1 = &C[(size_t)(m + 8) * Nc + n];
            if (accum) {
                float2 q0 = *(const float2*)p0, q1 = *(const float2*)p1;
                v00 += q0.x; v01 += q0.y; v10 += q1.x; v11 += q1.y;
            }
            *(float2*)p0 = make_float2(v00, v01);
            *(float2*)p1 = make_float2(v10, v11);
        }
}

// ---------------- 3xTF32 error-compensated GEMM + exact GELU (saliency s1) ----
__global__ __launch_bounds__(128) void s1_tf32x3(
    const float* __restrict__ A, const float* __restrict__ W,
    const float* __restrict__ bias, float* __restrict__ C, int Nc, int K)
{
    __shared__ unsigned Xhi[64][36], Xlo[64][36];
    __shared__ unsigned Whi[32][72], Wlo[32][72];
    int t = threadIdx.x & 3, g = (threadIdx.x >> 2) & 7, w = threadIdx.x >> 5;
    int m0 = blockIdx.y * 64, n0 = blockIdx.x * 64;

    float acc[8][4];
#pragma unroll
    for (int ni = 0; ni < 8; ni++)
#pragma unroll
        for (int c = 0; c < 4; c++) acc[ni][c] = 0.f;

    for (int k0 = 0; k0 < K; k0 += 32) {
#pragma unroll
        for (int it = 0; it < 4; it++) {
            int idx = it * 128 + threadIdx.x;
            int row = idx >> 3, c4 = (idx & 7) * 4;
            float4 v = *(const float4*)&A[(size_t)(m0 + row) * K + k0 + c4];
            float vv[4] = {v.x, v.y, v.z, v.w};
#pragma unroll
            for (int j = 0; j < 4; j++) {
                unsigned hi = f2tf(vv[j]);
                Xhi[row][c4 + j] = hi;
                Xlo[row][c4 + j] = f2tf(vv[j] - __uint_as_float(hi));
            }
        }
#pragma unroll
        for (int it = 0; it < 4; it++) {
            int idx = it * 128 + threadIdx.x;
            int kr = idx >> 4, n4 = (idx & 15) * 4;
            float4 v = *(const float4*)&W[(size_t)(k0 + kr) * Nc + n0 + n4];
            float vv[4] = {v.x, v.y, v.z, v.w};
#pragma unroll
            for (int j = 0; j < 4; j++) {
                unsigned hi = f2tf(vv[j]);
                Whi[kr][n4 + j] = hi;
                Wlo[kr][n4 + j] = f2tf(vv[j] - __uint_as_float(hi));
            }
        }
        __syncthreads();
#pragma unroll
        for (int ks = 0; ks < 4; ks++) {
            int kl = ks * 8;
            int r = w * 16 + g;
            unsigned ah[4], al[4];
            ah[0] = Xhi[r][kl + t];      ah[1] = Xhi[r + 8][kl + t];
            ah[2] = Xhi[r][kl + t + 4];  ah[3] = Xhi[r + 8][kl + t + 4];
            al[0] = Xlo[r][kl + t];      al[1] = Xlo[r + 8][kl + t];
            al[2] = Xlo[r][kl + t + 4];  al[3] = Xlo[r + 8][kl + t + 4];
#pragma unroll
            for (int ni = 0; ni < 8; ni++) {
                unsigned bh0 = Whi[kl + t][ni * 8 + g];
                unsigned bh1 = Whi[kl + t + 4][ni * 8 + g];
                unsigned bl0 = Wlo[kl + t][ni * 8 + g];
                unsigned bl1 = Wlo[kl + t + 4][ni * 8 + g];
                mma8(acc[ni][0], acc[ni][1], acc[ni][2], acc[ni][3],
                     al[0], al[1], al[2], al[3], bh0, bh1);
                mma8(acc[ni][0], acc[ni][1], acc[ni][2], acc[ni][3],
                     ah[0], ah[1], ah[2], ah[3], bl0, bl1);
                mma8(acc[ni][0], acc[ni][1], acc[ni][2], acc[ni][3],
                     ah[0], ah[1], ah[2], ah[3], bh0, bh1);
            }
        }
        __syncthreads();
    }
#pragma unroll
    for (int ni = 0; ni < 8; ni++) {
        int m = m0 + w * 16 + g;
        int n = n0 + ni * 8 + 2 * t;
        float bv0 = bias[n], bv1 = bias[n + 1];
        float vv[4] = {acc[ni][0] + bv0, acc[ni][1] + bv1,
                       acc[ni][2] + bv0, acc[ni][3] + bv1};
#pragma unroll
        for (int j = 0; j < 4; j++)
            vv[j] = 0.5f * vv[j] * (1.0f + erff(vv[j] * 0.70710678118654752f));
        *(float2*)&C[(size_t)m * Nc + n] = make_float2(vv[0], vv[1]);
        *(float2*)&C[(size_t)(m + 8) * Nc + n] = make_float2(vv[2], vv[3]);
    }
}

// ---------------- flash attention (Q frags hoisted to registers) ---------------
#define FLASH_SMEM ((128*68 + 64*68 + 64*72 + 64) * 4)
__global__ __launch_bounds__(256, 2) void flash_kernel()
{
    extern __shared__ unsigned sm[];
    unsigned* Qs = sm;                 // [128][68]
    unsigned* Ks = Qs + 128 * 68;      // [64][68]
    unsigned* Vs = Ks + 64 * 68;       // [64][72]
    int* maskCh  = (int*)(Vs + 64 * 72);   // [64]

    int hb = blockIdx.y;
    const float* buf = (hb < 4) ? g_lqkv : g_cqkv;
    int h = hb & 3;
    bool content = hb >= 4;
    int q0 = blockIdx.x * 128;
    int tid = threadIdx.x, lane = tid & 31, w = tid >> 5;
    int t = lane & 3, g = lane >> 2;
    int rb = w * 16 + g;
    int srcA = (g << 2) | (t >> 1);
    int srcB = srcA + 2;
    bool oddt = (t & 1);

#pragma unroll
    for (int it = 0; it < 8; it++) {
        int idx = it * 256 + tid;
        int r = idx >> 4, c = (idx & 15) * 4;
        float4 v = *(const float4*)&buf[(size_t)(q0 + r) * QKV + h * 64 + c];
        Qs[r * 68 + c + 0] = f2tf(v.x); Qs[r * 68 + c + 1] = f2tf(v.y);
        Qs[r * 68 + c + 2] = f2tf(v.z); Qs[r * 68 + c + 3] = f2tf(v.w);
    }
    __syncthreads();

    // hoist Q a-fragments: loop-invariant across all k-chunks (+32 regs)
    unsigned qf[8][4];
#pragma unroll
    for (int ks = 0; ks < 8; ks++) {
        int kl = ks * 8;
        qf[ks][0] = Qs[rb * 68 + kl + t];
        qf[ks][1] = Qs[(rb + 8) * 68 + kl + t];
        qf[ks][2] = Qs[rb * 68 + kl + t + 4];
        qf[ks][3] = Qs[(rb + 8) * 68 + kl + t + 4];
    }

    float m0 = -1e30f, m1 = -1e30f, l0 = 0.f, l1 = 0.f;
    float oacc[8][4];
#pragma unroll
    for (int ni = 0; ni < 8; ni++)
#pragma unroll
        for (int c = 0; c < 4; c++) oacc[ni][c] = 0.f;

    int nch = content ? NCHUNK_C : (NTOK / 64);
    for (int ch = 0; ch < nch; ch++) {
        int kc = ch * 64;
        __syncthreads();
#pragma unroll
        for (int it = 0; it < 4; it++) {
            int idx = it * 256 + tid;
            int r = idx >> 4, c = (idx & 15) * 4;
            int srow = content ? g_sel[kc + r] : (kc + r);
            int rr = srow < 0 ? 0 : srow;
            float4 kv = *(const float4*)&buf[(size_t)rr * QKV + 256 + h * 64 + c];
            Ks[r * 68 + c + 0] = f2tf(kv.x); Ks[r * 68 + c + 1] = f2tf(kv.y);
            Ks[r * 68 + c + 2] = f2tf(kv.z); Ks[r * 68 + c + 3] = f2tf(kv.w);
            float4 vv = *(const float4*)&buf[(size_t)rr * QKV + 512 + h * 64 + c];
            Vs[r * 72 + c + 0] = f2tf(vv.x); Vs[r * 72 + c + 1] = f2tf(vv.y);
            Vs[r * 72 + c + 2] = f2tf(vv.z); Vs[r * 72 + c + 3] = f2tf(vv.w);
        }
        if (tid < 64) maskCh[tid] = content ? (g_sel[kc + tid] >= 0) : 1;
        __syncthreads();

        float sacc[8][4];
#pragma unroll
        for (int ni = 0; ni < 8; ni++)
#pragma unroll
            for (int c = 0; c < 4; c++) sacc[ni][c] = 0.f;
#pragma unroll
        for (int ks = 0; ks < 8; ks++) {
            int kl = ks * 8;
#pragma unroll
            for (int ni = 0; ni < 8; ni++) {
                unsigned b0 = Ks[(ni * 8 + g) * 68 + kl + t];
                unsigned b1 = Ks[(ni * 8 + g) * 68 + kl + t + 4];
                mma8(sacc[ni][0], sacc[ni][1], sacc[ni][2], sacc[ni][3],
                     qf[ks][0], qf[ks][1], qf[ks][2], qf[ks][3], b0, b1);
            }
        }
        float cm0 = -1e30f, cm1 = -1e30f;
#pragma unroll
        for (int ni = 0; ni < 8; ni++) {
            int c0 = ni * 8 + 2 * t;
            bool on0 = maskCh[c0];
            bool on1 = maskCh[c0 + 1];
            sacc[ni][0] *= 0.125f; sacc[ni][1] *= 0.125f;
            sacc[ni][2] *= 0.125f; sacc[ni][3] *= 0.125f;
            cm0 = fmaxf(cm0, fmaxf(on0 ? sacc[ni][0] : -1e30f, on1 ? sacc[ni][1] : -1e30f));
            cm1 = fmaxf(cm1, fmaxf(on0 ? sacc[ni][2] : -1e30f, on1 ? sacc[ni][3] : -1e30f));
        }
        cm0 = fmaxf(cm0, __shfl_xor_sync(0xffffffffu, cm0, 1));
        cm0 = fmaxf(cm0, __shfl_xor_sync(0xffffffffu, cm0, 2));
        cm1 = fmaxf(cm1, __shfl_xor_sync(0xffffffffu, cm1, 1));
        cm1 = fmaxf(cm1, __shfl_xor_sync(0xffffffffu, cm1, 2));

        float mn0 = fmaxf(m0, cm0), mn1 = fmaxf(m1, cm1);
        float r0 = __expf(m0 - mn0), r1 = __expf(m1 - mn1);
        m0 = mn0; m1 = mn1;

        float es0 = 0.f, es1 = 0.f;
#pragma unroll
        for (int ni = 0; ni < 8; ni++) {
            int c0 = ni * 8 + 2 * t;
            bool on0 = maskCh[c0];
            bool on1 = maskCh[c0 + 1];
            float e00 = on0 ? __expf(sacc[ni][0] - mn0) : 0.f;
            float e01 = on1 ? __expf(sacc[ni][1] - mn0) : 0.f;
            float e10 = on0 ? __expf(sacc[ni][2] - mn1) : 0.f;
            float e11 = on1 ? __expf(sacc[ni][3] - mn1) : 0.f;
            es0 += e00 + e01; es1 += e10 + e11;
            sacc[ni][0] = e00; sacc[ni][1] = e01;
            sacc[ni][2] = e10; sacc[ni][3] = e11;
        }
        es0 += __shfl_xor_sync(0xffffffffu, es0, 1);
        es0 += __shfl_xor_sync(0xffffffffu, es0, 2);
        es1 += __shfl_xor_sync(0xffffffffu, es1, 1);
        es1 += __shfl_xor_sync(0xffffffffu, es1, 2);
        l0 = l0 * r0 + es0;
        l1 = l1 * r1 + es1;
#pragma unroll
        for (int ni = 0; ni < 8; ni++) {
            oacc[ni][0] *= r0; oacc[ni][1] *= r0;
            oacc[ni][2] *= r1; oacc[ni][3] *= r1;
        }

#pragma unroll
        for (int ks = 0; ks < 8; ks++) {
            float v00 = __shfl_sync(0xffffffffu, sacc[ks][0], srcA);
            float v01 = __shfl_sync(0xffffffffu, sacc[ks][1], srcA);
            float v10 = __shfl_sync(0xffffffffu, sacc[ks][2], srcA);
            float v11 = __shfl_sync(0xffffffffu, sacc[ks][3], srcA);
            float w00 = __shfl_sync(0xffffffffu, sacc[ks][0], srcB);
            float w01 = __shfl_sync(0xffffffffu, sacc[ks][1], srcB);
            float w10 = __shfl_sync(0xffffffffu, sacc[ks][2], srcB);
            float w11 = __shfl_sync(0xffffffffu, sacc[ks][3], srcB);
            unsigned a0 = f2tf(oddt ? v01 : v00);
            unsigned a1 = f2tf(oddt ? v11 : v10);
            unsigned a2 = f2tf(oddt ? w01 : w00);
            unsigned a3 = f2tf(oddt ? w11 : w10);
            int kl = ks * 8;
#pragma unroll
            for (int ni = 0; ni < 8; ni++) {
                unsigned b0 = Vs[(kl + t) * 72 + ni * 8 + g];
                unsigned b1 = Vs[(kl + t + 4) * 72 + ni * 8 + g];
                mma8(oacc[ni][0], oacc[ni][1], oacc[ni][2], oacc[ni][3],
                     a0, a1, a2, a3, b0, b1);
            }
        }
    }

    float iv0 = 1.0f / l0, iv1 = 1.0f / l1;
    int bB = hb >> 2;
    size_t ob = (size_t)bB * NTOK * 256;
    int r0i = q0 + rb, r1i = r0i + 8;
#pragma unroll
    for (int ni = 0; ni < 8; ni++) {
        int d = h * 64 + ni * 8 + 2 * t;
        *(float2*)&g_o[ob + (size_t)r0i * 256 + d] =
            make_float2(oacc[ni][0] * iv0, oacc[ni][1] * iv0);
        *(float2*)&g_o[ob + (size_t)r1i * 256 + d] =
            make_float2(oacc[ni][2] * iv1, oacc[ni][3] * iv1);
    }
    if (t == 0) {
        g_invl[hb * NTOK + r0i] = iv0; g_invl[hb * NTOK + r1i] = iv1;
        g_m[hb * NTOK + r0i] = m0;     g_m[hb * NTOK + r1i] = m1;
    }
}

// ---------------- attn local half: dense recompute + head-mean ----------------
#define ATTNL_SMEM ((128*68 + 128*68) * 4)
__global__ __launch_bounds__(256) void attn_local(float* __restrict__ attn)
{
    extern __shared__ unsigned sm[];
    unsigned* Qs = sm;                 // [128][68]
    unsigned* Ks = Qs + 128 * 68;      // [128][68]

    const float* buf = g_lqkv;
    int q0 = blockIdx.y * 128, k0 = blockIdx.x * 128;
    int tid = threadIdx.x, lane = tid & 31, w = tid >> 5;
    int t = lane & 3, g = lane >> 2;
    int rb = w * 16 + g;
    int r0i = q0 + rb, r1i = r0i + 8;

    float mh[4][2], iv[4][2];
#pragma unroll
    for (int h = 0; h < 4; h++) {
        mh[h][0] = g_m[h * NTOK + r0i];
        mh[h][1] = g_m[h * NTOK + r1i];
        iv[h][0] = g_invl[h * NTOK + r0i];
        iv[h][1] = g_invl[h * NTOK + r1i];
    }

    float facc[16][4];
#pragma unroll
    for (int ni = 0; ni < 16; ni++)
#pragma unroll
        for (int c = 0; c < 4; c++) facc[ni][c] = 0.f;

    for (int h = 0; h < 4; h++) {
        __syncthreads();
#pragma unroll
        for (int it = 0; it < 8; it++) {
            int idx = it * 256 + tid;
            int r = idx >> 4, c = (idx & 15) * 4;
            float4 v = *(const float4*)&buf[(size_t)(q0 + r) * QKV + h * 64 + c];
            Qs[r * 68 + c + 0] = f2tf(v.x); Qs[r * 68 + c + 1] = f2tf(v.y);
            Qs[r * 68 + c + 2] = f2tf(v.z); Qs[r * 68 + c + 3] = f2tf(v.w);
            float4 u = *(const float4*)&buf[(size_t)(k0 + r) * QKV + 256 + h * 64 + c];
            Ks[r * 68 + c + 0] = f2tf(u.x); Ks[r * 68 + c + 1] = f2tf(u.y);
            Ks[r * 68 + c + 2] = f2tf(u.z); Ks[r * 68 + c + 3] = f2tf(u.w);
        }
        __syncthreads();

        float sacc[16][4];
#pragma unroll
        for (int ni = 0; ni < 16; ni++)
#pragma unroll
            for (int c = 0; c < 4; c++) sacc[ni][c] = 0.f;
#pragma unroll
        for (int ks = 0; ks < 8; ks++) {
            int kl = ks * 8;
            unsigned a0 = Qs[rb * 68 + kl + t];
            unsigned a1 = Qs[(rb + 8) * 68 + kl + t];
            unsigned a2 = Qs[rb * 68 + kl + t + 4];
            unsigned a3 = Qs[(rb + 8) * 68 + kl + t + 4];
#pragma unroll
            for (int ni = 0; ni < 16; ni++) {
                unsigned b0 = Ks[(ni * 8 + g) * 68 + kl + t];
                unsigned b1 = Ks[(ni * 8 + g) * 68 + kl + t + 4];
                mma8(sacc[ni][0], sacc[ni][1], sacc[ni][2], sacc[ni][3],
                     a0, a1, a2, a3, b0, b1);
            }
        }
#pragma unroll
        for (int ni = 0; ni < 16; ni++) {
            facc[ni][0] += __expf(sacc[ni][0] * 0.125f - mh[h][0]) * iv[h][0];
            facc[ni][1] += __expf(sacc[ni][1] * 0.125f - mh[h][0]) * iv[h][0];
            facc[ni][2] += __expf(sacc[ni][2] * 0.125f - mh[h][1]) * iv[h][1];
            facc[ni][3] += __expf(sacc[ni][3] * 0.125f - mh[h][1]) * iv[h][1];
        }
    }
#pragma unroll
    for (int ni = 0; ni < 16; ni++) {
        int kk = k0 + ni * 8 + 2 * t;
        *(float2*)&attn[(size_t)r0i * NTOK + kk] =
            make_float2(facc[ni][0] * 0.25f, facc[ni][1] * 0.25f);
        *(float2*)&attn[(size_t)r1i * NTOK + kk] =
            make_float2(facc[ni][2] * 0.25f, facc[ni][3] * 0.25f);
    }
}

// ---------------- attn content half: only selected columns --------------------
#define ATTNC_SMEM ((128*68 + 64*68 + 64) * 4)
__global__ __launch_bounds__(256) void attn_content(float* __restrict__ attn)
{
    extern __shared__ unsigned sm[];
    unsigned* Qs = sm;                 // [128][68]
    unsigned* Ks = Qs + 128 * 68;      // [64][68]
    int* selS    = (int*)(Ks + 64 * 68);   // [64]

    const float* buf = g_cqkv;
    int q0 = blockIdx.y * 128;
    int k0s = blockIdx.x * 64;
    int tid = threadIdx.x, lane = tid & 31, w = tid >> 5;
    int t = lane & 3, g = lane >> 2;
    int rb = w * 16 + g;
    int r0i = q0 + rb, r1i = r0i + 8;

    if (tid < 64) selS[tid] = g_sel[k0s + tid];

    float mh[4][2], iv[4][2];
#pragma unroll
    for (int h = 0; h < 4; h++) {
        mh[h][0] = g_m[(4 + h) * NTOK + r0i];
        mh[h][1] = g_m[(4 + h) * NTOK + r1i];
        iv[h][0] = g_invl[(4 + h) * NTOK + r0i];
        iv[h][1] = g_invl[(4 + h) * NTOK + r1i];
    }

    float facc[8][4];
#pragma unroll
    for (int ni = 0; ni < 8; ni++)
#pragma unroll
        for (int c = 0; c < 4; c++) facc[ni][c] = 0.f;

    for (int h = 0; h < 4; h++) {
        __syncthreads();
#pragma unroll
        for (int it = 0; it < 8; it++) {
            int idx = it * 256 + tid;
            int r = idx >> 4, c = (idx & 15) * 4;
            float4 v = *(const float4*)&buf[(size_t)(q0 + r) * QKV + h * 64 + c];
            Qs[r * 68 + c + 0] = f2tf(v.x); Qs[r * 68 + c + 1] = f2tf(v.y);
            Qs[r * 68 + c + 2] = f2tf(v.z); Qs[r * 68 + c + 3] = f2tf(v.w);
        }
#pragma unroll
        for (int it = 0; it < 4; it++) {
            int idx = it * 256 + tid;
            int r = idx >> 4, c = (idx & 15) * 4;
            int srow = selS[r];
            int rr = srow < 0 ? 0 : srow;
            float4 u = *(const float4*)&buf[(size_t)rr * QKV + 256 + h * 64 + c];
            Ks[r * 68 + c + 0] = f2tf(u.x); Ks[r * 68 + c + 1] = f2tf(u.y);
            Ks[r * 68 + c + 2] = f2tf(u.z); Ks[r * 68 + c + 3] = f2tf(u.w);
        }
        __syncthreads();

        float sacc[8][4];
#pragma unroll
        for (int ni = 0; ni < 8; ni++)
#pragma unroll
            for (int c = 0; c < 4; c++) sacc[ni][c] = 0.f;
#pragma unroll
        for (int ks = 0; ks < 8; ks++) {
            int kl = ks * 8;
            unsigned a0 = Qs[rb * 68 + kl + t];
            unsigned a1 = Qs[(rb + 8) * 68 + kl + t];
            unsigned a2 = Qs[rb * 68 + kl + t + 4];
            unsigned a3 = Qs[(rb + 8) * 68 + kl + t + 4];
#pragma unroll
            for (int ni = 0; ni < 8; ni++) {
                unsigned b0 = Ks[(ni * 8 + g) * 68 + kl + t];
                unsigned b1 = Ks[(ni * 8 + g) * 68 + kl + t + 4];
                mma8(sacc[ni][0], sacc[ni][1], sacc[ni][2], sacc[ni][3],
                     a0, a1, a2, a3, b0, b1);
            }
        }
#pragma unroll
        for (int ni = 0; ni < 8; ni++) {
            facc[ni][0] += __expf(sacc[ni][0] * 0.125f - mh[h][0]) * iv[h][0];
            facc[ni][1] += __expf(sacc[ni][1] * 0.125f - mh[h][0]) * iv[h][0];
            facc[ni][2] += __expf(sacc[ni][2] * 0.125f - mh[h][1]) * iv[h][1];
            facc[ni][3] += __expf(sacc[ni][3] * 0.125f - mh[h][1]) * iv[h][1];
        }
    }
    float* arow0 = attn + ((size_t)(NTOK + r0i)) * NTOK;
    float* arow1 = attn + ((size_t)(NTOK + r1i)) * NTOK;
#pragma unroll
    for (int ni = 0; ni < 8; ni++) {
        int c0 = ni * 8 + 2 * t;
        int s0 = selS[c0], s1 = selS[c0 + 1];
        if (s0 >= 0) {
            arow0[s0] = facc[ni][0] * 0.25f;
            arow1[s0] = facc[ni][2] * 0.25f;
        }
        if (s1 >= 0) {
            arow0[s1] = facc[ni][1] * 0.25f;
            arow1[s1] = facc[ni][3] * 0.25f;
        }
    }
}

// ---------------- zero-fill content attn half ---------------------------------
__global__ __launch_bounds__(256) void fill_zero(float* __restrict__ p)
{
    size_t base = ((size_t)blockIdx.x * 256 + threadIdx.x) * 16;
    float4 z = make_float4(0.f, 0.f, 0.f, 0.f);
#pragma unroll
    for (int i = 0; i < 4; i++)
        *(float4*)&p[base + i * 4] = z;
}

// ---------------- saliency scores + exact top-k mask + compaction -------------
__global__ __launch_bounds__(256) void scores_kernel(
    const float* __restrict__ Ws2, const float* __restrict__ bs2)
{
    int t = blockIdx.x * 8 + (threadIdx.x >> 5);
    int lane = threadIdx.x & 31;
    const float* hp = g_h + (size_t)t * 256;
    float s = 0.f;
    for (int i = lane; i < 256; i += 32) s += hp[i] * Ws2[i];
#pragma unroll
    for (int off = 16; off; off >>= 1) s += __shfl_xor_sync(0xffffffffu, s, off);
    if (lane == 0) g_scores[t] = s + bs2[0];
}

__global__ __launch_bounds__(256) void mask_kernel()
{
    __shared__ float sc[NTOK];
    for (int i = threadIdx.x; i < NTOK; i += 256) sc[i] = g_scores[i];
    __syncthreads();
    int i = blockIdx.x * 256 + threadIdx.x;
    float si = sc[i];
    int cnt = 0;
    for (int j = 0; j < NTOK; j++) {
        float sj = sc[j];
        cnt += (sj > si) || (sj == si && j < i);
    }
    g_mask[i] = (cnt < KSEL) ? 1 : 0;
}

__global__ __launch_bounds__(1024) void compact_kernel()
{
    __shared__ int pre[1024];
    int tid = threadIdx.x;
    int base = tid * 4;
    int m0 = g_mask[base], m1 = g_mask[base + 1];
    int m2 = g_mask[base + 2], m3 = g_mask[base + 3];
    int s = m0 + m1 + m2 + m3;
    pre[tid] = s;
    __syncthreads();
    for (int off = 1; off < 1024; off <<= 1) {
        int v = (tid >= off) ? pre[tid - off] : 0;
        __syncthreads();
        pre[tid] += v;
        __syncthreads();
    }
    int p = pre[tid] - s;
    if (m0) g_sel[p++] = base;
    if (m1) g_sel[p++] = base + 1;
    if (m2) g_sel[p++] = base + 2;
    if (m3) g_sel[p++] = base + 3;
    if (tid < SELPAD - KSEL) g_sel[KSEL + tid] = -1;
}

// -----------------------------------------------------------------------------
extern "C" void kernel_launch(void* const* d_in, const int* in_sizes, int n_in,
                              void* d_out, int out_size)
{
    const float* x       = (const float*)d_in[0];
    const float* W_lqkv  = (const float*)d_in[1];
    const float* b_lqkv  = (const float*)d_in[2];
    const float* W_cqkv  = (const float*)d_in[3];
    const float* b_cqkv  = (const float*)d_in[4];
    const float* W_lproj = (const float*)d_in[5];
    const float* b_lproj = (const float*)d_in[6];
    const float* W_cproj = (const float*)d_in[7];
    const float* b_cproj = (const float*)d_in[8];
    const float* W_s1    = (const float*)d_in[9];
    const float* b_s1    = (const float*)d_in[10];
    const float* W_s2    = (const float*)d_in[11];
    const float* b_s2    = (const float*)d_in[12];

    float* out  = (float*)d_out;
    float* attn = out + (size_t)NTOK * DDIM;

    float *p_lqkv, *p_cqkv, *p_h, *p_o;
    cudaGetSymbolAddress((void**)&p_lqkv, g_lqkv);
    cudaGetSymbolAddress((void**)&p_cqkv, g_cqkv);
    cudaGetSymbolAddress((void**)&p_h,    g_h);
    cudaGetSymbolAddress((void**)&p_o,    g_o);

    static int attr_done = 0;
    if (!attr_done) {
        cudaFuncSetAttribute(flash_kernel,
            cudaFuncAttributeMaxDynamicSharedMemorySize, FLASH_SMEM);
        cudaFuncSetAttribute(attn_local,
            cudaFuncAttributeMaxDynamicSharedMemorySize, ATTNL_SMEM);
        cudaFuncSetAttribute(attn_content,
            cudaFuncAttributeMaxDynamicSharedMemorySize, ATTNC_SMEM);
        attr_done = 1;
    }

    // QKV projections (tf32 tensor cores)
    proj_tf32<<<dim3(12, 32), 128>>>(x, W_lqkv, b_lqkv, p_lqkv, QKV, DDIM, 0);
    proj_tf32<<<dim3(12, 32), 128>>>(x, W_cqkv, b_cqkv, p_cqkv, QKV, DDIM, 0);

    // saliency path (3xTF32 — fp32-equivalent accuracy, protects top-k boundary)
    s1_tf32x3<<<dim3(4, 64), 128>>>(x, W_s1, b_s1, p_h, 256, DDIM);
    scores_kernel<<<512, 256>>>(W_s2, b_s2);
    mask_kernel<<<16, 256>>>();
    compact_kernel<<<1, 1024>>>();

    // zero-fill content attn half (overwritten at selected columns below)
    fill_zero<<<4096, 256>>>(attn + (size_t)NTOK * NTOK);

    // attention core (flash; content heads use compacted key list)
    flash_kernel<<<dim3(32, 8), 256, FLASH_SMEM>>>();

    // attn output halves
    attn_local<<<dim3(32, 32), 256, ATTNL_SMEM>>>(attn);
    attn_content<<<dim3(NCHUNK_C, 32), 256, ATTNC_SMEM>>>(attn);

    // output projections (tf32, accumulate branches)
    proj_tf32<<<dim3(8, 32), 128>>>(p_o,              W_lproj, b_lproj, out, DDIM, 256, 0);
    proj_tf32<<<dim3(8, 32), 128>>>(p_o + NTOK * 256, W_cproj, b_cproj, out, DDIM, 256, 1);
}

// round 16
// speedup vs baseline: 1.1437x; 1.0437x over previous
#include <cuda_runtime.h>
#include <math.h>

#define NTOK 4096
#define DDIM 512
#define QKV  768
#define KSEL 819
#define SELPAD 832          // KSEL padded to multiple of 64
#define NCHUNK_C 13         // SELPAD / 64

// ---------------- scratch (device globals; no runtime allocation) -------------
__device__ float g_lqkv[NTOK * QKV];
__device__ float g_cqkv[NTOK * QKV];
__device__ float g_h[NTOK * 256];
__device__ float g_scores[NTOK];
__device__ int   g_mask[NTOK];
__device__ int   g_sel[SELPAD];
__device__ float g_m[8 * NTOK];
__device__ float g_invl[8 * NTOK];
__device__ float g_o[2 * NTOK * 256];

// ---------------- tf32 helpers ------------------------------------------------
__device__ __forceinline__ unsigned f2tf(float f) {
    unsigned r;
    asm("cvt.rna.tf32.f32 %0, %1;" : "=r"(r) : "f"(f));
    return r;
}
__device__ __forceinline__ void mma8(float& c0, float& c1, float& c2, float& c3,
                                     unsigned a0, unsigned a1, unsigned a2, unsigned a3,
                                     unsigned b0, unsigned b1)
{
    asm volatile(
        "mma.sync.aligned.m16n8k8.row.col.f32.tf32.tf32.f32 "
        "{%0,%1,%2,%3},{%4,%5,%6,%7},{%8,%9},{%0,%1,%2,%3};"
        : "+f"(c0), "+f"(c1), "+f"(c2), "+f"(c3)
        : "r"(a0), "r"(a1), "r"(a2), "r"(a3), "r"(b0), "r"(b1));
}
__device__ __forceinline__ void cp16(unsigned saddr, const void* gaddr) {
    asm volatile("cp.async.cg.shared.global [%0], [%1], 16;"
                 :: "r"(saddr), "l"(gaddr));
}
__device__ __forceinline__ void cp_commit() {
    asm volatile("cp.async.commit_group;");
}
template <int N>
__device__ __forceinline__ void cp_wait() {
    asm volatile("cp.async.wait_group %0;" :: "n"(N));
}

// ---------------- tf32 GEMM: C = A@W + bias (accum / tf32-round flags) --------
__global__ __launch_bounds__(128) void proj_tf32(
    const float* __restrict__ A, const float* __restrict__ W,
    const float* __restrict__ bias, float* __restrict__ C, int Nc, int K,
    int accum, int tfround)
{
    __shared__ unsigned Xs[128][36];
    __shared__ unsigned Ws[32][72];
    int t = threadIdx.x & 3, g = (threadIdx.x >> 2) & 7, w = threadIdx.x >> 5;
    int m0 = blockIdx.y * 128, n0 = blockIdx.x * 64;

    float acc[2][8][4];
#pragma unroll
    for (int mi = 0; mi < 2; mi++)
#pragma unroll
        for (int ni = 0; ni < 8; ni++)
#pragma unroll
            for (int c = 0; c < 4; c++) acc[mi][ni][c] = 0.f;

    for (int k0 = 0; k0 < K; k0 += 32) {
#pragma unroll
        for (int it = 0; it < 8; it++) {
            int idx = it * 128 + threadIdx.x;
            int row = idx >> 3, c4 = (idx & 7) * 4;
            float4 v = *(const float4*)&A[(size_t)(m0 + row) * K + k0 + c4];
            Xs[row][c4 + 0] = f2tf(v.x); Xs[row][c4 + 1] = f2tf(v.y);
            Xs[row][c4 + 2] = f2tf(v.z); Xs[row][c4 + 3] = f2tf(v.w);
        }
#pragma unroll
        for (int it = 0; it < 4; it++) {
            int idx = it * 128 + threadIdx.x;
            int kr = idx >> 4, n4 = (idx & 15) * 4;
            float4 v = *(const float4*)&W[(size_t)(k0 + kr) * Nc + n0 + n4];
            Ws[kr][n4 + 0] = f2tf(v.x); Ws[kr][n4 + 1] = f2tf(v.y);
            Ws[kr][n4 + 2] = f2tf(v.z); Ws[kr][n4 + 3] = f2tf(v.w);
        }
        __syncthreads();
#pragma unroll
        for (int ks = 0; ks < 4; ks++) {
            int kl = ks * 8;
            unsigned a[2][4];
#pragma unroll
            for (int mi = 0; mi < 2; mi++) {
                int r = w * 32 + mi * 16 + g;
                a[mi][0] = Xs[r][kl + t];      a[mi][1] = Xs[r + 8][kl + t];
                a[mi][2] = Xs[r][kl + t + 4];  a[mi][3] = Xs[r + 8][kl + t + 4];
            }
#pragma unroll
            for (int ni = 0; ni < 8; ni++) {
                unsigned b0 = Ws[kl + t][ni * 8 + g];
                unsigned b1 = Ws[kl + t + 4][ni * 8 + g];
#pragma unroll
                for (int mi = 0; mi < 2; mi++)
                    mma8(acc[mi][ni][0], acc[mi][ni][1], acc[mi][ni][2], acc[mi][ni][3],
                         a[mi][0], a[mi][1], a[mi][2], a[mi][3], b0, b1);
            }
        }
        __syncthreads();
    }
#pragma unroll
    for (int mi = 0; mi < 2; mi++)
#pragma unroll
        for (int ni = 0; ni < 8; ni++) {
            int m = m0 + w * 32 + mi * 16 + g;
            int n = n0 + ni * 8 + 2 * t;
            float bv0 = bias[n], bv1 = bias[n + 1];
            float v00 = acc[mi][ni][0] + bv0, v01 = acc[mi][ni][1] + bv1;
            float v10 = acc[mi][ni][2] + bv0, v11 = acc[mi][ni][3] + bv1;
            float* p0 = &C[(size_t)m * Nc + n];
            float* p1 = &C[(size_t)(m + 8) * Nc + n];
            if (accum) {
                float2 q0 = *(const float2*)p0, q1 = *(const float2*)p1;
                v00 += q0.x; v01 += q0.y; v10 += q1.x; v11 += q1.y;
            }
            if (tfround) {
                v00 = __uint_as_float(f2tf(v00)); v01 = __uint_as_float(f2tf(v01));
                v10 = __uint_as_float(f2tf(v10)); v11 = __uint_as_float(f2tf(v11));
            }
            *(float2*)p0 = make_float2(v00, v01);
            *(float2*)p1 = make_float2(v10, v11);
        }
}

// ---------------- 3xTF32 error-compensated GEMM + exact GELU (saliency s1) ----
__global__ __launch_bounds__(128) void s1_tf32x3(
    const float* __restrict__ A, const float* __restrict__ W,
    const float* __restrict__ bias, float* __restrict__ C, int Nc, int K)
{
    __shared__ unsigned Xhi[64][36], Xlo[64][36];
    __shared__ unsigned Whi[32][72], Wlo[32][72];
    int t = threadIdx.x & 3, g = (threadIdx.x >> 2) & 7, w = threadIdx.x >> 5;
    int m0 = blockIdx.y * 64, n0 = blockIdx.x * 64;

    float acc[8][4];
#pragma unroll
    for (int ni = 0; ni < 8; ni++)
#pragma unroll
        for (int c = 0; c < 4; c++) acc[ni][c] = 0.f;

    for (int k0 = 0; k0 < K; k0 += 32) {
#pragma unroll
        for (int it = 0; it < 4; it++) {
            int idx = it * 128 + threadIdx.x;
            int row = idx >> 3, c4 = (idx & 7) * 4;
            float4 v = *(const float4*)&A[(size_t)(m0 + row) * K + k0 + c4];
            float vv[4] = {v.x, v.y, v.z, v.w};
#pragma unroll
            for (int j = 0; j < 4; j++) {
                unsigned hi = f2tf(vv[j]);
                Xhi[row][c4 + j] = hi;
                Xlo[row][c4 + j] = f2tf(vv[j] - __uint_as_float(hi));
            }
        }
#pragma unroll
        for (int it = 0; it < 4; it++) {
            int idx = it * 128 + threadIdx.x;
            int kr = idx >> 4, n4 = (idx & 15) * 4;
            float4 v = *(const float4*)&W[(size_t)(k0 + kr) * Nc + n0 + n4];
            float vv[4] = {v.x, v.y, v.z, v.w};
#pragma unroll
            for (int j = 0; j < 4; j++) {
                unsigned hi = f2tf(vv[j]);
                Whi[kr][n4 + j] = hi;
                Wlo[kr][n4 + j] = f2tf(vv[j] - __uint_as_float(hi));
            }
        }
        __syncthreads();
#pragma unroll
        for (int ks = 0; ks < 4; ks++) {
            int kl = ks * 8;
            int r = w * 16 + g;
            unsigned ah[4], al[4];
            ah[0] = Xhi[r][kl + t];      ah[1] = Xhi[r + 8][kl + t];
            ah[2] = Xhi[r][kl + t + 4];  ah[3] = Xhi[r + 8][kl + t + 4];
            al[0] = Xlo[r][kl + t];      al[1] = Xlo[r + 8][kl + t];
            al[2] = Xlo[r][kl + t + 4];  al[3] = Xlo[r + 8][kl + t + 4];
#pragma unroll
            for (int ni = 0; ni < 8; ni++) {
                unsigned bh0 = Whi[kl + t][ni * 8 + g];
                unsigned bh1 = Whi[kl + t + 4][ni * 8 + g];
                unsigned bl0 = Wlo[kl + t][ni * 8 + g];
                unsigned bl1 = Wlo[kl + t + 4][ni * 8 + g];
                mma8(acc[ni][0], acc[ni][1], acc[ni][2], acc[ni][3],
                     al[0], al[1], al[2], al[3], bh0, bh1);
                mma8(acc[ni][0], acc[ni][1], acc[ni][2], acc[ni][3],
                     ah[0], ah[1], ah[2], ah[3], bl0, bl1);
                mma8(acc[ni][0], acc[ni][1], acc[ni][2], acc[ni][3],
                     ah[0], ah[1], ah[2], ah[3], bh0, bh1);
            }
        }
        __syncthreads();
    }
#pragma unroll
    for (int ni = 0; ni < 8; ni++) {
        int m = m0 + w * 16 + g;
        int n = n0 + ni * 8 + 2 * t;
        float bv0 = bias[n], bv1 = bias[n + 1];
        float vv[4] = {acc[ni][0] + bv0, acc[ni][1] + bv1,
                       acc[ni][2] + bv0, acc[ni][3] + bv1};
#pragma unroll
        for (int j = 0; j < 4; j++)
            vv[j] = 0.5f * vv[j] * (1.0f + erff(vv[j] * 0.70710678118654752f));
        *(float2*)&C[(size_t)m * Nc + n] = make_float2(vv[0], vv[1]);
        *(float2*)&C[(size_t)(m + 8) * Nc + n] = make_float2(vv[2], vv[3]);
    }
}

// ---------------- flash attention (cp.async double-buffered K/V) ---------------
// smem: Q 128x68 | K[2] 64x68 | V[2] 64x72 | mask[2][64]
#define FL_Q   0
#define FL_K   (128*68)
#define FL_V   (128*68 + 2*64*68)
#define FL_MK  (128*68 + 2*64*68 + 2*64*72)
#define FLASH_SMEM ((FL_MK + 2*64) * 4)
__global__ __launch_bounds__(256, 2) void flash_kernel()
{
    extern __shared__ unsigned sm[];
    unsigned* Qs = sm + FL_Q;
    int* maskS   = (int*)(sm + FL_MK);
    unsigned sbase = (unsigned)__cvta_generic_to_shared(sm);

    int hb = blockIdx.y;
    const float* buf = (hb < 4) ? g_lqkv : g_cqkv;
    int h = hb & 3;
    bool content = hb >= 4;
    int q0 = blockIdx.x * 128;
    int tid = threadIdx.x, lane = tid & 31, w = tid >> 5;
    int t = lane & 3, g = lane >> 2;
    int rb = w * 16 + g;
    int srcA = (g << 2) | (t >> 1);
    int srcB = srcA + 2;
    bool oddt = (t & 1);

    // Q tile (pre-rounded to tf32 by proj_tf32; copy bits)
#pragma unroll
    for (int it = 0; it < 8; it++) {
        int idx = it * 256 + tid;
        int r = idx >> 4, c = (idx & 15) * 4;
        float4 v = *(const float4*)&buf[(size_t)(q0 + r) * QKV + h * 64 + c];
        Qs[r * 68 + c + 0] = __float_as_uint(v.x);
        Qs[r * 68 + c + 1] = __float_as_uint(v.y);
        Qs[r * 68 + c + 2] = __float_as_uint(v.z);
        Qs[r * 68 + c + 3] = __float_as_uint(v.w);
    }

    int nch = content ? NCHUNK_C : (NTOK / 64);

    // async issue of chunk ch into buffer b
    auto issue = [&](int ch, int b) {
        int kc = ch * 64;
#pragma unroll
        for (int it = 0; it < 4; it++) {
            int idx = it * 256 + tid;
            int r = idx >> 4, c = (idx & 15) * 4;
            int srow = content ? g_sel[kc + r] : (kc + r);
            int rr = srow < 0 ? 0 : srow;
            const float* kp = &buf[(size_t)rr * QKV + 256 + h * 64 + c];
            const float* vp = &buf[(size_t)rr * QKV + 512 + h * 64 + c];
            cp16(sbase + (FL_K + b * (64 * 68) + r * 68 + c) * 4, kp);
            cp16(sbase + (FL_V + b * (64 * 72) + r * 72 + c) * 4, vp);
        }
        if (tid < 64) maskS[b * 64 + tid] = content ? (g_sel[kc + tid] >= 0) : 1;
    };

    issue(0, 0);
    cp_commit();

    float m0 = -1e30f, m1 = -1e30f, l0 = 0.f, l1 = 0.f;
    float oacc[8][4];
#pragma unroll
    for (int ni = 0; ni < 8; ni++)
#pragma unroll
        for (int c = 0; c < 4; c++) oacc[ni][c] = 0.f;

    for (int ch = 0; ch < nch; ch++) {
        int cur = ch & 1;
        unsigned* Ks = sm + FL_K + cur * (64 * 68);
        unsigned* Vs = sm + FL_V + cur * (64 * 72);
        int* maskCh  = maskS + cur * 64;

        if (ch + 1 < nch) {
            issue(ch + 1, cur ^ 1);
            cp_commit();
            cp_wait<1>();
        } else {
            cp_wait<0>();
        }
        __syncthreads();

        float sacc[8][4];
#pragma unroll
        for (int ni = 0; ni < 8; ni++)
#pragma unroll
            for (int c = 0; c < 4; c++) sacc[ni][c] = 0.f;
#pragma unroll
        for (int ks = 0; ks < 8; ks++) {
            int kl = ks * 8;
            unsigned a0 = Qs[rb * 68 + kl + t];
            unsigned a1 = Qs[(rb + 8) * 68 + kl + t];
            unsigned a2 = Qs[rb * 68 + kl + t + 4];
            unsigned a3 = Qs[(rb + 8) * 68 + kl + t + 4];
#pragma unroll
            for (int ni = 0; ni < 8; ni++) {
                unsigned b0 = Ks[(ni * 8 + g) * 68 + kl + t];
                unsigned b1 = Ks[(ni * 8 + g) * 68 + kl + t + 4];
                mma8(sacc[ni][0], sacc[ni][1], sacc[ni][2], sacc[ni][3],
                     a0, a1, a2, a3, b0, b1);
            }
        }
        float cm0 = -1e30f, cm1 = -1e30f;
#pragma unroll
        for (int ni = 0; ni < 8; ni++) {
            int c0 = ni * 8 + 2 * t;
            bool on0 = maskCh[c0];
            bool on1 = maskCh[c0 + 1];
            sacc[ni][0] *= 0.125f; sacc[ni][1] *= 0.125f;
            sacc[ni][2] *= 0.125f; sacc[ni][3] *= 0.125f;
            cm0 = fmaxf(cm0, fmaxf(on0 ? sacc[ni][0] : -1e30f, on1 ? sacc[ni][1] : -1e30f));
            cm1 = fmaxf(cm1, fmaxf(on0 ? sacc[ni][2] : -1e30f, on1 ? sacc[ni][3] : -1e30f));
        }
        cm0 = fmaxf(cm0, __shfl_xor_sync(0xffffffffu, cm0, 1));
        cm0 = fmaxf(cm0, __shfl_xor_sync(0xffffffffu, cm0, 2));
        cm1 = fmaxf(cm1, __shfl_xor_sync(0xffffffffu, cm1, 1));
        cm1 = fmaxf(cm1, __shfl_xor_sync(0xffffffffu, cm1, 2));

        float mn0 = fmaxf(m0, cm0), mn1 = fmaxf(m1, cm1);
        float r0 = __expf(m0 - mn0), r1 = __expf(m1 - mn1);
        m0 = mn0; m1 = mn1;

        float es0 = 0.f, es1 = 0.f;
#pragma unroll
        for (int ni = 0; ni < 8; ni++) {
            int c0 = ni * 8 + 2 * t;
            bool on0 = maskCh[c0];
            bool on1 = maskCh[c0 + 1];
            float e00 = on0 ? __expf(sacc[ni][0] - mn0) : 0.f;
            float e01 = on1 ? __expf(sacc[ni][1] - mn0) : 0.f;
            float e10 = on0 ? __expf(sacc[ni][2] - mn1) : 0.f;
            float e11 = on1 ? __expf(sacc[ni][3] - mn1) : 0.f;
            es0 += e00 + e01; es1 += e10 + e11;
            sacc[ni][0] = e00; sacc[ni][1] = e01;
            sacc[ni][2] = e10; sacc[ni][3] = e11;
        }
        es0 += __shfl_xor_sync(0xffffffffu, es0, 1);
        es0 += __shfl_xor_sync(0xffffffffu, es0, 2);
        es1 += __shfl_xor_sync(0xffffffffu, es1, 1);
        es1 += __shfl_xor_sync(0xffffffffu, es1, 2);
        l0 = l0 * r0 + es0;
        l1 = l1 * r1 + es1;
#pragma unroll
        for (int ni = 0; ni < 8; ni++) {
            oacc[ni][0] *= r0; oacc[ni][1] *= r0;
            oacc[ni][2] *= r1; oacc[ni][3] *= r1;
        }

#pragma unroll
        for (int ks = 0; ks < 8; ks++) {
            float v00 = __shfl_sync(0xffffffffu, sacc[ks][0], srcA);
            float v01 = __shfl_sync(0xffffffffu, sacc[ks][1], srcA);
            float v10 = __shfl_sync(0xffffffffu, sacc[ks][2], srcA);
            float v11 = __shfl_sync(0xffffffffu, sacc[ks][3], srcA);
            float w00 = __shfl_sync(0xffffffffu, sacc[ks][0], srcB);
            float w01 = __shfl_sync(0xffffffffu, sacc[ks][1], srcB);
            float w10 = __shfl_sync(0xffffffffu, sacc[ks][2], srcB);
            float w11 = __shfl_sync(0xffffffffu, sacc[ks][3], srcB);
            unsigned a0 = f2tf(oddt ? v01 : v00);
            unsigned a1 = f2tf(oddt ? v11 : v10);
            unsigned a2 = f2tf(oddt ? w01 : w00);
            unsigned a3 = f2tf(oddt ? w11 : w10);
            int kl = ks * 8;
#pragma unroll
            for (int ni = 0; ni < 8; ni++) {
                unsigned b0 = Vs[(kl + t) * 72 + ni * 8 + g];
                unsigned b1 = Vs[(kl + t + 4) * 72 + ni * 8 + g];
                mma8(oacc[ni][0], oacc[ni][1], oacc[ni][2], oacc[ni][3],
                     a0, a1, a2, a3, b0, b1);
            }
        }
        __syncthreads();   // protect buffer cur before it is re-issued at ch+2
    }

    float iv0 = 1.0f / l0, iv1 = 1.0f / l1;
    int bB = hb >> 2;
    size_t ob = (size_t)bB * NTOK * 256;
    int r0i = q0 + rb, r1i = r0i + 8;
#pragma unroll
    for (int ni = 0; ni < 8; ni++) {
        int d = h * 64 + ni * 8 + 2 * t;
        *(float2*)&g_o[ob + (size_t)r0i * 256 + d] =
            make_float2(oacc[ni][0] * iv0, oacc[ni][1] * iv0);
        *(float2*)&g_o[ob + (size_t)r1i * 256 + d] =
            make_float2(oacc[ni][2] * iv1, oacc[ni][3] * iv1);
    }
    if (t == 0) {
        g_invl[hb * NTOK + r0i] = iv0; g_invl[hb * NTOK + r1i] = iv1;
        g_m[hb * NTOK + r0i] = m0;     g_m[hb * NTOK + r1i] = m1;
    }
}

// ---------------- attn local half: dense recompute + head-mean ----------------
#define ATTNL_SMEM ((128*68 + 128*68) * 4)
__global__ __launch_bounds__(256) void attn_local(float* __restrict__ attn)
{
    extern __shared__ unsigned sm[];
    unsigned* Qs = sm;                 // [128][68]
    unsigned* Ks = Qs + 128 * 68;      // [128][68]

    const float* buf = g_lqkv;
    int q0 = blockIdx.y * 128, k0 = blockIdx.x * 128;
    int tid = threadIdx.x, lane = tid & 31, w = tid >> 5;
    int t = lane & 3, g = lane >> 2;
    int rb = w * 16 + g;
    int r0i = q0 + rb, r1i = r0i + 8;

    float mh[4][2], iv[4][2];
#pragma unroll
    for (int h = 0; h < 4; h++) {
        mh[h][0] = g_m[h * NTOK + r0i];
        mh[h][1] = g_m[h * NTOK + r1i];
        iv[h][0] = g_invl[h * NTOK + r0i];
        iv[h][1] = g_invl[h * NTOK + r1i];
    }

    float facc[16][4];
#pragma unroll
    for (int ni = 0; ni < 16; ni++)
#pragma unroll
        for (int c = 0; c < 4; c++) facc[ni][c] = 0.f;

    for (int h = 0; h < 4; h++) {
        __syncthreads();
#pragma unroll
        for (int it = 0; it < 8; it++) {
            int idx = it * 256 + tid;
            int r = idx >> 4, c = (idx & 15) * 4;
            float4 v = *(const float4*)&buf[(size_t)(q0 + r) * QKV + h * 64 + c];
            Qs[r * 68 + c + 0] = __float_as_uint(v.x);
            Qs[r * 68 + c + 1] = __float_as_uint(v.y);
            Qs[r * 68 + c + 2] = __float_as_uint(v.z);
            Qs[r * 68 + c + 3] = __float_as_uint(v.w);
            float4 u = *(const float4*)&buf[(size_t)(k0 + r) * QKV + 256 + h * 64 + c];
            Ks[r * 68 + c + 0] = __float_as_uint(u.x);
            Ks[r * 68 + c + 1] = __float_as_uint(u.y);
            Ks[r * 68 + c + 2] = __float_as_uint(u.z);
            Ks[r * 68 + c + 3] = __float_as_uint(u.w);
        }
        __syncthreads();

        float sacc[16][4];
#pragma unroll
        for (int ni = 0; ni < 16; ni++)
#pragma unroll
            for (int c = 0; c < 4; c++) sacc[ni][c] = 0.f;
#pragma unroll
        for (int ks = 0; ks < 8; ks++) {
            int kl = ks * 8;
            unsigned a0 = Qs[rb * 68 + kl + t];
            unsigned a1 = Qs[(rb + 8) * 68 + kl + t];
            unsigned a2 = Qs[rb * 68 + kl + t + 4];
            unsigned a3 = Qs[(rb + 8) * 68 + kl + t + 4];
#pragma unroll
            for (int ni = 0; ni < 16; ni++) {
                unsigned b0 = Ks[(ni * 8 + g) * 68 + kl + t];
                unsigned b1 = Ks[(ni * 8 + g) * 68 + kl + t + 4];
                mma8(sacc[ni][0], sacc[ni][1], sacc[ni][2], sacc[ni][3],
                     a0, a1, a2, a3, b0, b1);
            }
        }
#pragma unroll
        for (int ni = 0; ni < 16; ni++) {
            facc[ni][0] += __expf(sacc[ni][0] * 0.125f - mh[h][0]) * iv[h][0];
            facc[ni][1] += __expf(sacc[ni][1] * 0.125f - mh[h][0]) * iv[h][0];
            facc[ni][2] += __expf(sacc[ni][2] * 0.125f - mh[h][1]) * iv[h][1];
            facc[ni][3] += __expf(sacc[ni][3] * 0.125f - mh[h][1]) * iv[h][1];
        }
    }
#pragma unroll
    for (int ni = 0; ni < 16; ni++) {
        int kk = k0 + ni * 8 + 2 * t;
        *(float2*)&attn[(size_t)r0i * NTOK + kk] =
            make_float2(facc[ni][0] * 0.25f, facc[ni][1] * 0.25f);
        *(float2*)&attn[(size_t)r1i * NTOK + kk] =
            make_float2(facc[ni][2] * 0.25f, facc[ni][3] * 0.25f);
    }
}

// ---------------- attn content half: only selected columns --------------------
#define ATTNC_SMEM ((128*68 + 64*68 + 64) * 4)
__global__ __launch_bounds__(256) void attn_content(float* __restrict__ attn)
{
    extern __shared__ unsigned sm[];
    unsigned* Qs = sm;                 // [128][68]
    unsigned* Ks = Qs + 128 * 68;      // [64][68]
    int* selS    = (int*)(Ks + 64 * 68);   // [64]

    const float* buf = g_cqkv;
    int q0 = blockIdx.y * 128;
    int k0s = blockIdx.x * 64;
    int tid = threadIdx.x, lane = tid & 31, w = tid >> 5;
    int t = lane & 3, g = lane >> 2;
    int rb = w * 16 + g;
    int r0i = q0 + rb, r1i = r0i + 8;

    if (tid < 64) selS[tid] = g_sel[k0s + tid];

    float mh[4][2], iv[4][2];
#pragma unroll
    for (int h = 0; h < 4; h++) {
        mh[h][0] = g_m[(4 + h) * NTOK + r0i];
        mh[h][1] = g_m[(4 + h) * NTOK + r1i];
        iv[h][0] = g_invl[(4 + h) * NTOK + r0i];
        iv[h][1] = g_invl[(4 + h) * NTOK + r1i];
    }

    float facc[8][4];
#pragma unroll
    for (int ni = 0; ni < 8; ni++)
#pragma unroll
        for (int c = 0; c < 4; c++) facc[ni][c] = 0.f;

    for (int h = 0; h < 4; h++) {
        __syncthreads();
#pragma unroll
        for (int it = 0; it < 8; it++) {
            int idx = it * 256 + tid;
            int r = idx >> 4, c = (idx & 15) * 4;
            float4 v = *(const float4*)&buf[(size_t)(q0 + r) * QKV + h * 64 + c];
            Qs[r * 68 + c + 0] = __float_as_uint(v.x);
            Qs[r * 68 + c + 1] = __float_as_uint(v.y);
            Qs[r * 68 + c + 2] = __float_as_uint(v.z);
            Qs[r * 68 + c + 3] = __float_as_uint(v.w);
        }
#pragma unroll
        for (int it = 0; it < 4; it++) {
            int idx = it * 256 + tid;
            int r = idx >> 4, c = (idx & 15) * 4;
            int srow = selS[r];
            int rr = srow < 0 ? 0 : srow;
            float4 u = *(const float4*)&buf[(size_t)rr * QKV + 256 + h * 64 + c];
            Ks[r * 68 + c + 0] = __float_as_uint(u.x);
            Ks[r * 68 + c + 1] = __float_as_uint(u.y);
            Ks[r * 68 + c + 2] = __float_as_uint(u.z);
            Ks[r * 68 + c + 3] = __float_as_uint(u.w);
        }
        __syncthreads();

        float sacc[8][4];
#pragma unroll
        for (int ni = 0; ni < 8; ni++)
#pragma unroll
            for (int c = 0; c < 4; c++) sacc[ni][c] = 0.f;
#pragma unroll
        for (int ks = 0; ks < 8; ks++) {
            int kl = ks * 8;
            unsigned a0 = Qs[rb * 68 + kl + t];
            unsigned a1 = Qs[(rb + 8) * 68 + kl + t];
            unsigned a2 = Qs[rb * 68 + kl + t + 4];
            unsigned a3 = Qs[(rb + 8) * 68 + kl + t + 4];
#pragma unroll
            for (int ni = 0; ni < 8; ni++) {
                unsigned b0 = Ks[(ni * 8 + g) * 68 + kl + t];
                unsigned b1 = Ks[(ni * 8 + g) * 68 + kl + t + 4];
                mma8(sacc[ni][0], sacc[ni][1], sacc[ni][2], sacc[ni][3],
                     a0, a1, a2, a3, b0, b1);
            }
        }
#pragma unroll
        for (int ni = 0; ni < 8; ni++) {
            facc[ni][0] += __expf(sacc[ni][0] * 0.125f - mh[h][0]) * iv[h][0];
            facc[ni][1] += __expf(sacc[ni][1] * 0.125f - mh[h][0]) * iv[h][0];
            facc[ni][2] += __expf(sacc[ni][2] * 0.125f - mh[h][1]) * iv[h][1];
            facc[ni][3] += __expf(sacc[ni][3] * 0.125f - mh[h][1]) * iv[h][1];
        }
    }
    float* arow0 = attn + ((size_t)(NTOK + r0i)) * NTOK;
    float* arow1 = attn + ((size_t)(NTOK + r1i)) * NTOK;
#pragma unroll
    for (int ni = 0; ni < 8; ni++) {
        int c0 = ni * 8 + 2 * t;
        int s0 = selS[c0], s1 = selS[c0 + 1];
        if (s0 >= 0) {
            arow0[s0] = facc[ni][0] * 0.25f;
            arow1[s0] = facc[ni][2] * 0.25f;
        }
        if (s1 >= 0) {
            arow0[s1] = facc[ni][1] * 0.25f;
            arow1[s1] = facc[ni][3] * 0.25f;
        }
    }
}

// ---------------- zero-fill content attn half ---------------------------------
__global__ __launch_bounds__(256) void fill_zero(float* __restrict__ p)
{
    size_t base = ((size_t)blockIdx.x * 256 + threadIdx.x) * 16;
    float4 z = make_float4(0.f, 0.f, 0.f, 0.f);
#pragma unroll
    for (int i = 0; i < 4; i++)
        *(float4*)&p[base + i * 4] = z;
}

// ---------------- saliency scores + exact top-k mask + compaction -------------
__global__ __launch_bounds__(256) void scores_kernel(
    const float* __restrict__ Ws2, const float* __restrict__ bs2)
{
    int t = blockIdx.x * 8 + (threadIdx.x >> 5);
    int lane = threadIdx.x & 31;
    const float* hp = g_h + (size_t)t * 256;
    float s = 0.f;
    for (int i = lane; i < 256; i += 32) s += hp[i] * Ws2[i];
#pragma unroll
    for (int off = 16; off; off >>= 1) s += __shfl_xor_sync(0xffffffffu, s, off);
    if (lane == 0) g_scores[t] = s + bs2[0];
}

__global__ __launch_bounds__(256) void mask_kernel()
{
    __shared__ float sc[NTOK];
    for (int i = threadIdx.x; i < NTOK; i += 256) sc[i] = g_scores[i];
    __syncthreads();
    int i = blockIdx.x * 256 + threadIdx.x;
    float si = sc[i];
    int cnt = 0;
    for (int j = 0; j < NTOK; j++) {
        float sj = sc[j];
        cnt += (sj > si) || (sj == si && j < i);
    }
    g_mask[i] = (cnt < KSEL) ? 1 : 0;
}

__global__ __launch_bounds__(1024) void compact_kernel()
{
    __shared__ int pre[1024];
    int tid = threadIdx.x;
    int base = tid * 4;
    int m0 = g_mask[base], m1 = g_mask[base + 1];
    int m2 = g_mask[base + 2], m3 = g_mask[base + 3];
    int s = m0 + m1 + m2 + m3;
    pre[tid] = s;
    __syncthreads();
    for (int off = 1; off < 1024; off <<= 1) {
        int v = (tid >= off) ? pre[tid - off] : 0;
        __syncthreads();
        pre[tid] += v;
        __syncthreads();
    }
    int p = pre[tid] - s;
    if (m0) g_sel[p++] = base;
    if (m1) g_sel[p++] = base + 1;
    if (m2) g_sel[p++] = base + 2;
    if (m3) g_sel[p++] = base + 3;
    if (tid < SELPAD - KSEL) g_sel[KSEL + tid] = -1;
}

// -----------------------------------------------------------------------------
extern "C" void kernel_launch(void* const* d_in, const int* in_sizes, int n_in,
                              void* d_out, int out_size)
{
    const float* x       = (const float*)d_in[0];
    const float* W_lqkv  = (const float*)d_in[1];
    const float* b_lqkv  = (const float*)d_in[2];
    const float* W_cqkv  = (const float*)d_in[3];
    const float* b_cqkv  = (const float*)d_in[4];
    const float* W_lproj = (const float*)d_in[5];
    const float* b_lproj = (const float*)d_in[6];
    const float* W_cproj = (const float*)d_in[7];
    const float* b_cproj = (const float*)d_in[8];
    const float* W_s1    = (const float*)d_in[9];
    const float* b_s1    = (const float*)d_in[10];
    const float* W_s2    = (const float*)d_in[11];
    const float* b_s2    = (const float*)d_in[12];

    float* out  = (float*)d_out;
    float* attn = out + (size_t)NTOK * DDIM;

    float *p_lqkv, *p_cqkv, *p_h, *p_o;
    cudaGetSymbolAddress((void**)&p_lqkv, g_lqkv);
    cudaGetSymbolAddress((void**)&p_cqkv, g_cqkv);
    cudaGetSymbolAddress((void**)&p_h,    g_h);
    cudaGetSymbolAddress((void**)&p_o,    g_o);

    static int attr_done = 0;
    if (!attr_done) {
        cudaFuncSetAttribute(flash_kernel,
            cudaFuncAttributeMaxDynamicSharedMemorySize, FLASH_SMEM);
        cudaFuncSetAttribute(attn_local,
            cudaFuncAttributeMaxDynamicSharedMemorySize, ATTNL_SMEM);
        cudaFuncSetAttribute(attn_content,
            cudaFuncAttributeMaxDynamicSharedMemorySize, ATTNC_SMEM);
        attr_done = 1;
    }

    // QKV projections (tf32 tensor cores; outputs pre-rounded to tf32)
    proj_tf32<<<dim3(12, 32), 128>>>(x, W_lqkv, b_lqkv, p_lqkv, QKV, DDIM, 0, 1);
    proj_tf32<<<dim3(12, 32), 128>>>(x, W_cqkv, b_cqkv, p_cqkv, QKV, DDIM, 0, 1);

    // saliency path (3xTF32 — fp32-equivalent accuracy, protects top-k boundary)
    s1_tf32x3<<<dim3(4, 64), 128>>>(x, W_s1, b_s1, p_h, 256, DDIM);
    scores_kernel<<<512, 256>>>(W_s2, b_s2);
    mask_kernel<<<16, 256>>>();
    compact_kernel<<<1, 1024>>>();

    // zero-fill content attn half (overwritten at selected columns below)
    fill_zero<<<4096, 256>>>(attn + (size_t)NTOK * NTOK);

    // attention core (flash; cp.async double-buffered K/V)
    flash_kernel<<<dim3(32, 8), 256, FLASH_SMEM>>>();

    // attn output halves
    attn_local<<<dim3(32, 32), 256, ATTNL_SMEM>>>(attn);
    attn_content<<<dim3(NCHUNK_C, 32), 256, ATTNC_SMEM>>>(attn);

    // output projections (tf32, accumulate branches; exact fp32 stores)
    proj_tf32<<<dim3(8, 32), 128>>>(p_o,              W_lproj, b_lproj, out, DDIM, 256, 0, 0);
    proj_tf32<<<dim3(8, 32), 128>>>(p_o + NTOK * 256, W_cproj, b_cproj, out, DDIM, 256, 1, 0);
}

// round 17
// speedup vs baseline: 1.1515x; 1.0068x over previous
#include <cuda_runtime.h>
#include <math.h>

#define NTOK 4096
#define DDIM 512
#define QKV  768
#define KSEL 819
#define SELPAD 832          // KSEL padded to multiple of 64
#define NCHUNK_C 13         // SELPAD / 64

// ---------------- scratch (device globals; no runtime allocation) -------------
__device__ float g_lqkv[NTOK * QKV];
__device__ float g_cqkv[NTOK * QKV];
__device__ float g_h[NTOK * 256];
__device__ float g_scores[NTOK];
__device__ int   g_mask[NTOK];
__device__ int   g_sel[SELPAD];
__device__ float g_m[8 * NTOK];
__device__ float g_invl[8 * NTOK];
__device__ float g_o[2 * NTOK * 256];

// ---------------- tf32 helpers ------------------------------------------------
__device__ __forceinline__ unsigned f2tf(float f) {
    unsigned r;
    asm("cvt.rna.tf32.f32 %0, %1;" : "=r"(r) : "f"(f));
    return r;
}
__device__ __forceinline__ void mma8(float& c0, float& c1, float& c2, float& c3,
                                     unsigned a0, unsigned a1, unsigned a2, unsigned a3,
                                     unsigned b0, unsigned b1)
{
    asm volatile(
        "mma.sync.aligned.m16n8k8.row.col.f32.tf32.tf32.f32 "
        "{%0,%1,%2,%3},{%4,%5,%6,%7},{%8,%9},{%0,%1,%2,%3};"
        : "+f"(c0), "+f"(c1), "+f"(c2), "+f"(c3)
        : "r"(a0), "r"(a1), "r"(a2), "r"(a3), "r"(b0), "r"(b1));
}
__device__ __forceinline__ void cp16(unsigned saddr, const void* gaddr) {
    asm volatile("cp.async.cg.shared.global [%0], [%1], 16;"
                 :: "r"(saddr), "l"(gaddr));
}
__device__ __forceinline__ void cp_commit() {
    asm volatile("cp.async.commit_group;");
}
template <int N>
__device__ __forceinline__ void cp_wait() {
    asm volatile("cp.async.wait_group %0;" :: "n"(N));
}

// ---------------- tf32 GEMM: C = A@W + bias (accum / tf32-round flags) --------
__global__ __launch_bounds__(128) void proj_tf32(
    const float* __restrict__ A, const float* __restrict__ W,
    const float* __restrict__ bias, float* __restrict__ C, int Nc, int K,
    int accum, int tfround)
{
    __shared__ unsigned Xs[128][36];
    __shared__ unsigned Ws[32][72];
    int t = threadIdx.x & 3, g = (threadIdx.x >> 2) & 7, w = threadIdx.x >> 5;
    int m0 = blockIdx.y * 128, n0 = blockIdx.x * 64;

    float acc[2][8][4];
#pragma unroll
    for (int mi = 0; mi < 2; mi++)
#pragma unroll
        for (int ni = 0; ni < 8; ni++)
#pragma unroll
            for (int c = 0; c < 4; c++) acc[mi][ni][c] = 0.f;

    for (int k0 = 0; k0 < K; k0 += 32) {
#pragma unroll
        for (int it = 0; it < 8; it++) {
            int idx = it * 128 + threadIdx.x;
            int row = idx >> 3, c4 = (idx & 7) * 4;
            float4 v = *(const float4*)&A[(size_t)(m0 + row) * K + k0 + c4];
            Xs[row][c4 + 0] = f2tf(v.x); Xs[row][c4 + 1] = f2tf(v.y);
            Xs[row][c4 + 2] = f2tf(v.z); Xs[row][c4 + 3] = f2tf(v.w);
        }
#pragma unroll
        for (int it = 0; it < 4; it++) {
            int idx = it * 128 + threadIdx.x;
            int kr = idx >> 4, n4 = (idx & 15) * 4;
            float4 v = *(const float4*)&W[(size_t)(k0 + kr) * Nc + n0 + n4];
            Ws[kr][n4 + 0] = f2tf(v.x); Ws[kr][n4 + 1] = f2tf(v.y);
            Ws[kr][n4 + 2] = f2tf(v.z); Ws[kr][n4 + 3] = f2tf(v.w);
        }
        __syncthreads();
#pragma unroll
        for (int ks = 0; ks < 4; ks++) {
            int kl = ks * 8;
            unsigned a[2][4];
#pragma unroll
            for (int mi = 0; mi < 2; mi++) {
                int r = w * 32 + mi * 16 + g;
                a[mi][0] = Xs[r][kl + t];      a[mi][1] = Xs[r + 8][kl + t];
                a[mi][2] = Xs[r][kl + t + 4];  a[mi][3] = Xs[r + 8][kl + t + 4];
            }
#pragma unroll
            for (int ni = 0; ni < 8; ni++) {
                unsigned b0 = Ws[kl + t][ni * 8 + g];
                unsigned b1 = Ws[kl + t + 4][ni * 8 + g];
#pragma unroll
                for (int mi = 0; mi < 2; mi++)
                    mma8(acc[mi][ni][0], acc[mi][ni][1], acc[mi][ni][2], acc[mi][ni][3],
                         a[mi][0], a[mi][1], a[mi][2], a[mi][3], b0, b1);
            }
        }
        __syncthreads();
    }
#pragma unroll
    for (int mi = 0; mi < 2; mi++)
#pragma unroll
        for (int ni = 0; ni < 8; ni++) {
            int m = m0 + w * 32 + mi * 16 + g;
            int n = n0 + ni * 8 + 2 * t;
            float bv0 = bias[n], bv1 = bias[n + 1];
            float v00 = acc[mi][ni][0] + bv0, v01 = acc[mi][ni][1] + bv1;
            float v10 = acc[mi][ni][2] + bv0, v11 = acc[mi][ni][3] + bv1;
            float* p0 = &C[(size_t)m * Nc + n];
            float* p1 = &C[(size_t)(m + 8) * Nc + n];
            if (accum) {
                float2 q0 = *(const float2*)p0, q1 = *(const float2*)p1;
                v00 += q0.x; v01 += q0.y; v10 += q1.x; v11 += q1.y;
            }
            if (tfround) {
                v00 = __uint_as_float(f2tf(v00)); v01 = __uint_as_float(f2tf(v01));
                v10 = __uint_as_float(f2tf(v10)); v11 = __uint_as_float(f2tf(v11));
            }
            *(float2*)p0 = make_float2(v00, v01);
            *(float2*)p1 = make_float2(v10, v11);
        }
}

// ---------------- 3xTF32 error-compensated GEMM + exact GELU (saliency s1) ----
__global__ __launch_bounds__(128) void s1_tf32x3(
    const float* __restrict__ A, const float* __restrict__ W,
    const float* __restrict__ bias, float* __restrict__ C, int Nc, int K)
{
    __shared__ unsigned Xhi[64][36], Xlo[64][36];
    __shared__ unsigned Whi[32][72], Wlo[32][72];
    int t = threadIdx.x & 3, g = (threadIdx.x >> 2) & 7, w = threadIdx.x >> 5;
    int m0 = blockIdx.y * 64, n0 = blockIdx.x * 64;

    float acc[8][4];
#pragma unroll
    for (int ni = 0; ni < 8; ni++)
#pragma unroll
        for (int c = 0; c < 4; c++) acc[ni][c] = 0.f;

    for (int k0 = 0; k0 < K; k0 += 32) {
#pragma unroll
        for (int it = 0; it < 4; it++) {
            int idx = it * 128 + threadIdx.x;
            int row = idx >> 3, c4 = (idx & 7) * 4;
            float4 v = *(const float4*)&A[(size_t)(m0 + row) * K + k0 + c4];
            float vv[4] = {v.x, v.y, v.z, v.w};
#pragma unroll
            for (int j = 0; j < 4; j++) {
                unsigned hi = f2tf(vv[j]);
                Xhi[row][c4 + j] = hi;
                Xlo[row][c4 + j] = f2tf(vv[j] - __uint_as_float(hi));
            }
        }
#pragma unroll
        for (int it = 0; it < 4; it++) {
            int idx = it * 128 + threadIdx.x;
            int kr = idx >> 4, n4 = (idx & 15) * 4;
            float4 v = *(const float4*)&W[(size_t)(k0 + kr) * Nc + n0 + n4];
            float vv[4] = {v.x, v.y, v.z, v.w};
#pragma unroll
            for (int j = 0; j < 4; j++) {
                unsigned hi = f2tf(vv[j]);
                Whi[kr][n4 + j] = hi;
                Wlo[kr][n4 + j] = f2tf(vv[j] - __uint_as_float(hi));
            }
        }
        __syncthreads();
#pragma unroll
        for (int ks = 0; ks < 4; ks++) {
            int kl = ks * 8;
            int r = w * 16 + g;
            unsigned ah[4], al[4];
            ah[0] = Xhi[r][kl + t];      ah[1] = Xhi[r + 8][kl + t];
            ah[2] = Xhi[r][kl + t + 4];  ah[3] = Xhi[r + 8][kl + t + 4];
            al[0] = Xlo[r][kl + t];      al[1] = Xlo[r + 8][kl + t];
            al[2] = Xlo[r][kl + t + 4];  al[3] = Xlo[r + 8][kl + t + 4];
#pragma unroll
            for (int ni = 0; ni < 8; ni++) {
                unsigned bh0 = Whi[kl + t][ni * 8 + g];
                unsigned bh1 = Whi[kl + t + 4][ni * 8 + g];
                unsigned bl0 = Wlo[kl + t][ni * 8 + g];
                unsigned bl1 = Wlo[kl + t + 4][ni * 8 + g];
                mma8(acc[ni][0], acc[ni][1], acc[ni][2], acc[ni][3],
                     al[0], al[1], al[2], al[3], bh0, bh1);
                mma8(acc[ni][0], acc[ni][1], acc[ni][2], acc[ni][3],
                     ah[0], ah[1], ah[2], ah[3], bl0, bl1);
                mma8(acc[ni][0], acc[ni][1], acc[ni][2], acc[ni][3],
                     ah[0], ah[1], ah[2], ah[3], bh0, bh1);
            }
        }
        __syncthreads();
    }
#pragma unroll
    for (int ni = 0; ni < 8; ni++) {
        int m = m0 + w * 16 + g;
        int n = n0 + ni * 8 + 2 * t;
        float bv0 = bias[n], bv1 = bias[n + 1];
        float vv[4] = {acc[ni][0] + bv0, acc[ni][1] + bv1,
                       acc[ni][2] + bv0, acc[ni][3] + bv1};
#pragma unroll
        for (int j = 0; j < 4; j++)
            vv[j] = 0.5f * vv[j] * (1.0f + erff(vv[j] * 0.70710678118654752f));
        *(float2*)&C[(size_t)m * Nc + n] = make_float2(vv[0], vv[1]);
        *(float2*)&C[(size_t)(m + 8) * Nc + n] = make_float2(vv[2], vv[3]);
    }
}

// ---------------- flash attention (cp.async double-buffered K/V) ---------------
#define FL_Q   0
#define FL_K   (128*68)
#define FL_V   (128*68 + 2*64*68)
#define FL_MK  (128*68 + 2*64*68 + 2*64*72)
#define FLASH_SMEM ((FL_MK + 2*64) * 4)
__global__ __launch_bounds__(256, 2) void flash_kernel()
{
    extern __shared__ unsigned sm[];
    unsigned* Qs = sm + FL_Q;
    int* maskS   = (int*)(sm + FL_MK);
    unsigned sbase = (unsigned)__cvta_generic_to_shared(sm);

    int hb = blockIdx.y;
    const float* buf = (hb < 4) ? g_lqkv : g_cqkv;
    int h = hb & 3;
    bool content = hb >= 4;
    int q0 = blockIdx.x * 128;
    int tid = threadIdx.x, lane = tid & 31, w = tid >> 5;
    int t = lane & 3, g = lane >> 2;
    int rb = w * 16 + g;
    int srcA = (g << 2) | (t >> 1);
    int srcB = srcA + 2;
    bool oddt = (t & 1);

#pragma unroll
    for (int it = 0; it < 8; it++) {
        int idx = it * 256 + tid;
        int r = idx >> 4, c = (idx & 15) * 4;
        float4 v = *(const float4*)&buf[(size_t)(q0 + r) * QKV + h * 64 + c];
        Qs[r * 68 + c + 0] = __float_as_uint(v.x);
        Qs[r * 68 + c + 1] = __float_as_uint(v.y);
        Qs[r * 68 + c + 2] = __float_as_uint(v.z);
        Qs[r * 68 + c + 3] = __float_as_uint(v.w);
    }

    int nch = content ? NCHUNK_C : (NTOK / 64);

    auto issue = [&](int ch, int b) {
        int kc = ch * 64;
#pragma unroll
        for (int it = 0; it < 4; it++) {
            int idx = it * 256 + tid;
            int r = idx >> 4, c = (idx & 15) * 4;
            int srow = content ? g_sel[kc + r] : (kc + r);
            int rr = srow < 0 ? 0 : srow;
            const float* kp = &buf[(size_t)rr * QKV + 256 + h * 64 + c];
            const float* vp = &buf[(size_t)rr * QKV + 512 + h * 64 + c];
            cp16(sbase + (FL_K + b * (64 * 68) + r * 68 + c) * 4, kp);
            cp16(sbase + (FL_V + b * (64 * 72) + r * 72 + c) * 4, vp);
        }
        if (tid < 64) maskS[b * 64 + tid] = content ? (g_sel[kc + tid] >= 0) : 1;
    };

    issue(0, 0);
    cp_commit();

    float m0 = -1e30f, m1 = -1e30f, l0 = 0.f, l1 = 0.f;
    float oacc[8][4];
#pragma unroll
    for (int ni = 0; ni < 8; ni++)
#pragma unroll
        for (int c = 0; c < 4; c++) oacc[ni][c] = 0.f;

    for (int ch = 0; ch < nch; ch++) {
        int cur = ch & 1;
        unsigned* Ks = sm + FL_K + cur * (64 * 68);
        unsigned* Vs = sm + FL_V + cur * (64 * 72);
        int* maskCh  = maskS + cur * 64;

        if (ch + 1 < nch) {
            issue(ch + 1, cur ^ 1);
            cp_commit();
            cp_wait<1>();
        } else {
            cp_wait<0>();
        }
        __syncthreads();

        float sacc[8][4];
#pragma unroll
        for (int ni = 0; ni < 8; ni++)
#pragma unroll
            for (int c = 0; c < 4; c++) sacc[ni][c] = 0.f;
#pragma unroll
        for (int ks = 0; ks < 8; ks++) {
            int kl = ks * 8;
            unsigned a0 = Qs[rb * 68 + kl + t];
            unsigned a1 = Qs[(rb + 8) * 68 + kl + t];
            unsigned a2 = Qs[rb * 68 + kl + t + 4];
            unsigned a3 = Qs[(rb + 8) * 68 + kl + t + 4];
#pragma unroll
            for (int ni = 0; ni < 8; ni++) {
                unsigned b0 = Ks[(ni * 8 + g) * 68 + kl + t];
                unsigned b1 = Ks[(ni * 8 + g) * 68 + kl + t + 4];
                mma8(sacc[ni][0], sacc[ni][1], sacc[ni][2], sacc[ni][3],
                     a0, a1, a2, a3, b0, b1);
            }
        }
        float cm0 = -1e30f, cm1 = -1e30f;
#pragma unroll
        for (int ni = 0; ni < 8; ni++) {
            int c0 = ni * 8 + 2 * t;
            bool on0 = maskCh[c0];
            bool on1 = maskCh[c0 + 1];
            sacc[ni][0] *= 0.125f; sacc[ni][1] *= 0.125f;
            sacc[ni][2] *= 0.125f; sacc[ni][3] *= 0.125f;
            cm0 = fmaxf(cm0, fmaxf(on0 ? sacc[ni][0] : -1e30f, on1 ? sacc[ni][1] : -1e30f));
            cm1 = fmaxf(cm1, fmaxf(on0 ? sacc[ni][2] : -1e30f, on1 ? sacc[ni][3] : -1e30f));
        }
        cm0 = fmaxf(cm0, __shfl_xor_sync(0xffffffffu, cm0, 1));
        cm0 = fmaxf(cm0, __shfl_xor_sync(0xffffffffu, cm0, 2));
        cm1 = fmaxf(cm1, __shfl_xor_sync(0xffffffffu, cm1, 1));
        cm1 = fmaxf(cm1, __shfl_xor_sync(0xffffffffu, cm1, 2));

        float mn0 = fmaxf(m0, cm0), mn1 = fmaxf(m1, cm1);
        float r0 = __expf(m0 - mn0), r1 = __expf(m1 - mn1);
        m0 = mn0; m1 = mn1;

        float es0 = 0.f, es1 = 0.f;
#pragma unroll
        for (int ni = 0; ni < 8; ni++) {
            int c0 = ni * 8 + 2 * t;
            bool on0 = maskCh[c0];
            bool on1 = maskCh[c0 + 1];
            float e00 = on0 ? __expf(sacc[ni][0] - mn0) : 0.f;
            float e01 = on1 ? __expf(sacc[ni][1] - mn0) : 0.f;
            float e10 = on0 ? __expf(sacc[ni][2] - mn1) : 0.f;
            float e11 = on1 ? __expf(sacc[ni][3] - mn1) : 0.f;
            es0 += e00 + e01; es1 += e10 + e11;
            sacc[ni][0] = e00; sacc[ni][1] = e01;
            sacc[ni][2] = e10; sacc[ni][3] = e11;
        }
        es0 += __shfl_xor_sync(0xffffffffu, es0, 1);
        es0 += __shfl_xor_sync(0xffffffffu, es0, 2);
        es1 += __shfl_xor_sync(0xffffffffu, es1, 1);
        es1 += __shfl_xor_sync(0xffffffffu, es1, 2);
        l0 = l0 * r0 + es0;
        l1 = l1 * r1 + es1;
#pragma unroll
        for (int ni = 0; ni < 8; ni++) {
            oacc[ni][0] *= r0; oacc[ni][1] *= r0;
            oacc[ni][2] *= r1; oacc[ni][3] *= r1;
        }

#pragma unroll
        for (int ks = 0; ks < 8; ks++) {
            float v00 = __shfl_sync(0xffffffffu, sacc[ks][0], srcA);
            float v01 = __shfl_sync(0xffffffffu, sacc[ks][1], srcA);
            float v10 = __shfl_sync(0xffffffffu, sacc[ks][2], srcA);
            float v11 = __shfl_sync(0xffffffffu, sacc[ks][3], srcA);
            float w00 = __shfl_sync(0xffffffffu, sacc[ks][0], srcB);
            float w01 = __shfl_sync(0xffffffffu, sacc[ks][1], srcB);
            float w10 = __shfl_sync(0xffffffffu, sacc[ks][2], srcB);
            float w11 = __shfl_sync(0xffffffffu, sacc[ks][3], srcB);
            unsigned a0 = f2tf(oddt ? v01 : v00);
            unsigned a1 = f2tf(oddt ? v11 : v10);
            unsigned a2 = f2tf(oddt ? w01 : w00);
            unsigned a3 = f2tf(oddt ? w11 : w10);
            int kl = ks * 8;
#pragma unroll
            for (int ni = 0; ni < 8; ni++) {
                unsigned b0 = Vs[(kl + t) * 72 + ni * 8 + g];
                unsigned b1 = Vs[(kl + t + 4) * 72 + ni * 8 + g];
                mma8(oacc[ni][0], oacc[ni][1], oacc[ni][2], oacc[ni][3],
                     a0, a1, a2, a3, b0, b1);
            }
        }
        __syncthreads();
    }

    float iv0 = 1.0f / l0, iv1 = 1.0f / l1;
    int bB = hb >> 2;
    size_t ob = (size_t)bB * NTOK * 256;
    int r0i = q0 + rb, r1i = r0i + 8;
#pragma unroll
    for (int ni = 0; ni < 8; ni++) {
        int d = h * 64 + ni * 8 + 2 * t;
        *(float2*)&g_o[ob + (size_t)r0i * 256 + d] =
            make_float2(oacc[ni][0] * iv0, oacc[ni][1] * iv0);
        *(float2*)&g_o[ob + (size_t)r1i * 256 + d] =
            make_float2(oacc[ni][2] * iv1, oacc[ni][3] * iv1);
    }
    if (t == 0) {
        g_invl[hb * NTOK + r0i] = iv0; g_invl[hb * NTOK + r1i] = iv1;
        g_m[hb * NTOK + r0i] = m0;     g_m[hb * NTOK + r1i] = m1;
    }
}

// -------- attn local half: warp tile 32q x 64k (better b-frag reuse) ----------
#define ATTNL_SMEM ((128*68 + 128*68) * 4)
__global__ __launch_bounds__(256) void attn_local(float* __restrict__ attn)
{
    extern __shared__ unsigned sm[];
    unsigned* Qs = sm;                 // [128][68]
    unsigned* Ks = Qs + 128 * 68;      // [128][68]

    const float* buf = g_lqkv;
    int q0 = blockIdx.y * 128, k0 = blockIdx.x * 128;
    int tid = threadIdx.x, lane = tid & 31, w = tid >> 5;
    int t = lane & 3, g = lane >> 2;
    int wq = w & 3, wk = w >> 2;       // 4 q-strips x 2 k-halves
    int rb = wq * 32 + g;
    int kb = wk * 64;

    float mh[4][4], iv[4][4];
#pragma unroll
    for (int h = 0; h < 4; h++)
#pragma unroll
        for (int mi = 0; mi < 2; mi++) {
            int r0i = q0 + rb + mi * 16, r1i = r0i + 8;
            mh[h][mi * 2]     = g_m[h * NTOK + r0i];
            mh[h][mi * 2 + 1] = g_m[h * NTOK + r1i];
            iv[h][mi * 2]     = g_invl[h * NTOK + r0i];
            iv[h][mi * 2 + 1] = g_invl[h * NTOK + r1i];
        }

    float facc[2][8][4];
#pragma unroll
    for (int mi = 0; mi < 2; mi++)
#pragma unroll
        for (int ni = 0; ni < 8; ni++)
#pragma unroll
            for (int c = 0; c < 4; c++) facc[mi][ni][c] = 0.f;

    for (int h = 0; h < 4; h++) {
        __syncthreads();
#pragma unroll
        for (int it = 0; it < 8; it++) {
            int idx = it * 256 + tid;
            int r = idx >> 4, c = (idx & 15) * 4;
            float4 v = *(const float4*)&buf[(size_t)(q0 + r) * QKV + h * 64 + c];
            Qs[r * 68 + c + 0] = __float_as_uint(v.x);
            Qs[r * 68 + c + 1] = __float_as_uint(v.y);
            Qs[r * 68 + c + 2] = __float_as_uint(v.z);
            Qs[r * 68 + c + 3] = __float_as_uint(v.w);
            float4 u = *(const float4*)&buf[(size_t)(k0 + r) * QKV + 256 + h * 64 + c];
            Ks[r * 68 + c + 0] = __float_as_uint(u.x);
            Ks[r * 68 + c + 1] = __float_as_uint(u.y);
            Ks[r * 68 + c + 2] = __float_as_uint(u.z);
            Ks[r * 68 + c + 3] = __float_as_uint(u.w);
        }
        __syncthreads();

        float sacc[2][8][4];
#pragma unroll
        for (int mi = 0; mi < 2; mi++)
#pragma unroll
            for (int ni = 0; ni < 8; ni++)
#pragma unroll
                for (int c = 0; c < 4; c++) sacc[mi][ni][c] = 0.f;
#pragma unroll
        for (int ks = 0; ks < 8; ks++) {
            int kl = ks * 8;
            unsigned a[2][4];
#pragma unroll
            for (int mi = 0; mi < 2; mi++) {
                int r = rb + mi * 16;
                a[mi][0] = Qs[r * 68 + kl + t];
                a[mi][1] = Qs[(r + 8) * 68 + kl + t];
                a[mi][2] = Qs[r * 68 + kl + t + 4];
                a[mi][3] = Qs[(r + 8) * 68 + kl + t + 4];
            }
#pragma unroll
            for (int ni = 0; ni < 8; ni++) {
                unsigned b0 = Ks[(kb + ni * 8 + g) * 68 + kl + t];
                unsigned b1 = Ks[(kb + ni * 8 + g) * 68 + kl + t + 4];
#pragma unroll
                for (int mi = 0; mi < 2; mi++)
                    mma8(sacc[mi][ni][0], sacc[mi][ni][1], sacc[mi][ni][2], sacc[mi][ni][3],
                         a[mi][0], a[mi][1], a[mi][2], a[mi][3], b0, b1);
            }
        }
#pragma unroll
        for (int mi = 0; mi < 2; mi++)
#pragma unroll
            for (int ni = 0; ni < 8; ni++) {
                facc[mi][ni][0] += __expf(sacc[mi][ni][0] * 0.125f - mh[h][mi * 2]) * iv[h][mi * 2];
                facc[mi][ni][1] += __expf(sacc[mi][ni][1] * 0.125f - mh[h][mi * 2]) * iv[h][mi * 2];
                facc[mi][ni][2] += __expf(sacc[mi][ni][2] * 0.125f - mh[h][mi * 2 + 1]) * iv[h][mi * 2 + 1];
                facc[mi][ni][3] += __expf(sacc[mi][ni][3] * 0.125f - mh[h][mi * 2 + 1]) * iv[h][mi * 2 + 1];
            }
    }
#pragma unroll
    for (int mi = 0; mi < 2; mi++)
#pragma unroll
        for (int ni = 0; ni < 8; ni++) {
            int r0i = q0 + rb + mi * 16, r1i = r0i + 8;
            int kk = k0 + kb + ni * 8 + 2 * t;
            *(float2*)&attn[(size_t)r0i * NTOK + kk] =
                make_float2(facc[mi][ni][0] * 0.25f, facc[mi][ni][1] * 0.25f);
            *(float2*)&attn[(size_t)r1i * NTOK + kk] =
                make_float2(facc[mi][ni][2] * 0.25f, facc[mi][ni][3] * 0.25f);
        }
}

// ---------------- attn content half: only selected columns --------------------
#define ATTNC_SMEM ((128*68 + 64*68 + 64) * 4)
__global__ __launch_bounds__(256) void attn_content(float* __restrict__ attn)
{
    extern __shared__ unsigned sm[];
    unsigned* Qs = sm;                 // [128][68]
    unsigned* Ks = Qs + 128 * 68;      // [64][68]
    int* selS    = (int*)(Ks + 64 * 68);   // [64]

    const float* buf = g_cqkv;
    int q0 = blockIdx.y * 128;
    int k0s = blockIdx.x * 64;
    int tid = threadIdx.x, lane = tid & 31, w = tid >> 5;
    int t = lane & 3, g = lane >> 2;
    int rb = w * 16 + g;
    int r0i = q0 + rb, r1i = r0i + 8;

    if (tid < 64) selS[tid] = g_sel[k0s + tid];

    float mh[4][2], iv[4][2];
#pragma unroll
    for (int h = 0; h < 4; h++) {
        mh[h][0] = g_m[(4 + h) * NTOK + r0i];
        mh[h][1] = g_m[(4 + h) * NTOK + r1i];
        iv[h][0] = g_invl[(4 + h) * NTOK + r0i];
        iv[h][1] = g_invl[(4 + h) * NTOK + r1i];
    }

    float facc[8][4];
#pragma unroll
    for (int ni = 0; ni < 8; ni++)
#pragma unroll
        for (int c = 0; c < 4; c++) facc[ni][c] = 0.f;

    for (int h = 0; h < 4; h++) {
        __syncthreads();
#pragma unroll
        for (int it = 0; it < 8; it++) {
            int idx = it * 256 + tid;
            int r = idx >> 4, c = (idx & 15) * 4;
            float4 v = *(const float4*)&buf[(size_t)(q0 + r) * QKV + h * 64 + c];
            Qs[r * 68 + c + 0] = __float_as_uint(v.x);
            Qs[r * 68 + c + 1] = __float_as_uint(v.y);
            Qs[r * 68 + c + 2] = __float_as_uint(v.z);
            Qs[r * 68 + c + 3] = __float_as_uint(v.w);
        }
#pragma unroll
        for (int it = 0; it < 4; it++) {
            int idx = it * 256 + tid;
            int r = idx >> 4, c = (idx & 15) * 4;
            int srow = selS[r];
            int rr = srow < 0 ? 0 : srow;
            float4 u = *(const float4*)&buf[(size_t)rr * QKV + 256 + h * 64 + c];
            Ks[r * 68 + c + 0] = __float_as_uint(u.x);
            Ks[r * 68 + c + 1] = __float_as_uint(u.y);
            Ks[r * 68 + c + 2] = __float_as_uint(u.z);
            Ks[r * 68 + c + 3] = __float_as_uint(u.w);
        }
        __syncthreads();

        float sacc[8][4];
#pragma unroll
        for (int ni = 0; ni < 8; ni++)
#pragma unroll
            for (int c = 0; c < 4; c++) sacc[ni][c] = 0.f;
#pragma unroll
        for (int ks = 0; ks < 8; ks++) {
            int kl = ks * 8;
            unsigned a0 = Qs[rb * 68 + kl + t];
            unsigned a1 = Qs[(rb + 8) * 68 + kl + t];
            unsigned a2 = Qs[rb * 68 + kl + t + 4];
            unsigned a3 = Qs[(rb + 8) * 68 + kl + t + 4];
#pragma unroll
            for (int ni = 0; ni < 8; ni++) {
                unsigned b0 = Ks[(ni * 8 + g) * 68 + kl + t];
                unsigned b1 = Ks[(ni * 8 + g) * 68 + kl + t + 4];
                mma8(sacc[ni][0], sacc[ni][1], sacc[ni][2], sacc[ni][3],
                     a0, a1, a2, a3, b0, b1);
            }
        }
#pragma unroll
        for (int ni = 0; ni < 8; ni++) {
            facc[ni][0] += __expf(sacc[ni][0] * 0.125f - mh[h][0]) * iv[h][0];
            facc[ni][1] += __expf(sacc[ni][1] * 0.125f - mh[h][0]) * iv[h][0];
            facc[ni][2] += __expf(sacc[ni][2] * 0.125f - mh[h][1]) * iv[h][1];
            facc[ni][3] += __expf(sacc[ni][3] * 0.125f - mh[h][1]) * iv[h][1];
        }
    }
    float* arow0 = attn + ((size_t)(NTOK + r0i)) * NTOK;
    float* arow1 = attn + ((size_t)(NTOK + r1i)) * NTOK;
#pragma unroll
    for (int ni = 0; ni < 8; ni++) {
        int c0 = ni * 8 + 2 * t;
        int s0 = selS[c0], s1 = selS[c0 + 1];
        if (s0 >= 0) {
            arow0[s0] = facc[ni][0] * 0.25f;
            arow1[s0] = facc[ni][2] * 0.25f;
        }
        if (s1 >= 0) {
            arow0[s1] = facc[ni][1] * 0.25f;
            arow1[s1] = facc[ni][3] * 0.25f;
        }
    }
}

// ---------------- zero-fill content attn half ---------------------------------
__global__ __launch_bounds__(256) void fill_zero(float* __restrict__ p)
{
    size_t base = ((size_t)blockIdx.x * 256 + threadIdx.x) * 16;
    float4 z = make_float4(0.f, 0.f, 0.f, 0.f);
#pragma unroll
    for (int i = 0; i < 4; i++)
        *(float4*)&p[base + i * 4] = z;
}

// ---------------- saliency scores + exact top-k mask + compaction -------------
__global__ __launch_bounds__(256) void scores_kernel(
    const float* __restrict__ Ws2, const float* __restrict__ bs2)
{
    int t = blockIdx.x * 8 + (threadIdx.x >> 5);
    int lane = threadIdx.x & 31;
    const float* hp = g_h + (size_t)t * 256;
    float s = 0.f;
    for (int i = lane; i < 256; i += 32) s += hp[i] * Ws2[i];
#pragma unroll
    for (int off = 16; off; off >>= 1) s += __shfl_xor_sync(0xffffffffu, s, off);
    if (lane == 0) g_scores[t] = s + bs2[0];
}

__global__ __launch_bounds__(256) void mask_kernel()
{
    __shared__ float sc[NTOK];
    for (int i = threadIdx.x; i < NTOK; i += 256) sc[i] = g_scores[i];
    __syncthreads();
    int i = blockIdx.x * 256 + threadIdx.x;
    float si = sc[i];
    int cnt = 0;
    for (int j = 0; j < NTOK; j++) {
        float sj = sc[j];
        cnt += (sj > si) || (sj == si && j < i);
    }
    g_mask[i] = (cnt < KSEL) ? 1 : 0;
}

__global__ __launch_bounds__(1024) void compact_kernel()
{
    __shared__ int pre[1024];
    int tid = threadIdx.x;
    int base = tid * 4;
    int m0 = g_mask[base], m1 = g_mask[base + 1];
    int m2 = g_mask[base + 2], m3 = g_mask[base + 3];
    int s = m0 + m1 + m2 + m3;
    pre[tid] = s;
    __syncthreads();
    for (int off = 1; off < 1024; off <<= 1) {
        int v = (tid >= off) ? pre[tid - off] : 0;
        __syncthreads();
        pre[tid] += v;
        __syncthreads();
    }
    int p = pre[tid] - s;
    if (m0) g_sel[p++] = base;
    if (m1) g_sel[p++] = base + 1;
    if (m2) g_sel[p++] = base + 2;
    if (m3) g_sel[p++] = base + 3;
    if (tid < SELPAD - KSEL) g_sel[KSEL + tid] = -1;
}

// -----------------------------------------------------------------------------
extern "C" void kernel_launch(void* const* d_in, const int* in_sizes, int n_in,
                              void* d_out, int out_size)
{
    const float* x       = (const float*)d_in[0];
    const float* W_lqkv  = (const float*)d_in[1];
    const float* b_lqkv  = (const float*)d_in[2];
    const float* W_cqkv  = (const float*)d_in[3];
    const float* b_cqkv  = (const float*)d_in[4];
    const float* W_lproj = (const float*)d_in[5];
    const float* b_lproj = (const float*)d_in[6];
    const float* W_cproj = (const float*)d_in[7];
    const float* b_cproj = (const float*)d_in[8];
    const float* W_s1    = (const float*)d_in[9];
    const float* b_s1    = (const float*)d_in[10];
    const float* W_s2    = (const float*)d_in[11];
    const float* b_s2    = (const float*)d_in[12];

    float* out  = (float*)d_out;
    float* attn = out + (size_t)NTOK * DDIM;

    float *p_lqkv, *p_cqkv, *p_h, *p_o;
    cudaGetSymbolAddress((void**)&p_lqkv, g_lqkv);
    cudaGetSymbolAddress((void**)&p_cqkv, g_cqkv);
    cudaGetSymbolAddress((void**)&p_h,    g_h);
    cudaGetSymbolAddress((void**)&p_o,    g_o);

    static int attr_done = 0;
    if (!attr_done) {
        cudaFuncSetAttribute(flash_kernel,
            cudaFuncAttributeMaxDynamicSharedMemorySize, FLASH_SMEM);
        cudaFuncSetAttribute(attn_local,
            cudaFuncAttributeMaxDynamicSharedMemorySize, ATTNL_SMEM);
        cudaFuncSetAttribute(attn_content,
            cudaFuncAttributeMaxDynamicSharedMemorySize, ATTNC_SMEM);
        attr_done = 1;
    }

    // QKV projections (tf32 tensor cores; outputs pre-rounded to tf32)
    proj_tf32<<<dim3(12, 32), 128>>>(x, W_lqkv, b_lqkv, p_lqkv, QKV, DDIM, 0, 1);
    proj_tf32<<<dim3(12, 32), 128>>>(x, W_cqkv, b_cqkv, p_cqkv, QKV, DDIM, 0, 1);

    // saliency path (3xTF32 — fp32-equivalent accuracy, protects top-k boundary)
    s1_tf32x3<<<dim3(4, 64), 128>>>(x, W_s1, b_s1, p_h, 256, DDIM);
    scores_kernel<<<512, 256>>>(W_s2, b_s2);
    mask_kernel<<<16, 256>>>();
    compact_kernel<<<1, 1024>>>();

    // zero-fill content attn half (overwritten at selected columns below)
    fill_zero<<<4096, 256>>>(attn + (size_t)NTOK * NTOK);

    // attention core (flash; cp.async double-buffered K/V)
    flash_kernel<<<dim3(32, 8), 256, FLASH_SMEM>>>();

    // attn output halves
    attn_local<<<dim3(32, 32), 256, ATTNL_SMEM>>>(attn);
    attn_content<<<dim3(NCHUNK_C, 32), 256, ATTNC_SMEM>>>(attn);

    // output projections (tf32, accumulate branches; exact fp32 stores)
    proj_tf32<<<dim3(8, 32), 128>>>(p_o,              W_lproj, b_lproj, out, DDIM, 256, 0, 0);
    proj_tf32<<<dim3(8, 32), 128>>>(p_o + NTOK * 256, W_cproj, b_cproj, out, DDIM, 256, 1, 0);
}